// round 1
// baseline (speedup 1.0000x reference)
#include <cuda_runtime.h>
#include <cuda_bf16.h>
#include <math.h>

// Problem constants
#define BATCH 2
#define SEQ   2048
#define HID   4096
#define NH    32
#define NKV   8
#define HD    128
#define TOKENS (BATCH*SEQ)          // 4096
#define QROW (NH*HD)                // 4096
#define KROW (NKV*HD)               // 1024

// ---------------- scratch (no cudaMalloc allowed) ----------------
__device__ float g_q[(long)TOKENS * QROW];     // 64 MB
__device__ float g_k[(long)TOKENS * KROW];     // 16 MB
__device__ float g_v[(long)TOKENS * KROW];     // 16 MB
__device__ float g_attn[(long)TOKENS * QROW];  // 64 MB

// =================================================================
// GEMM:  C[m,n] = sum_k A[m,k] * B[n,k]
// A: M x K row-major, B: N x K row-major, C: M x N row-major.
// M,N multiples of 128; K multiple of 8.
// 128x128 tile, BK=8, 256 threads, 8x8 per-thread register tile.
// =================================================================
__global__ __launch_bounds__(256)
void gemm_nt(const float* __restrict__ A, const float* __restrict__ B,
             float* __restrict__ C, int M, int N, int K)
{
    __shared__ float As[8][128];
    __shared__ float Bs[8][128];

    const int tid = threadIdx.x;
    const int m0 = blockIdx.y * 128;
    const int n0 = blockIdx.x * 128;
    const int tr = tid >> 4;       // 0..15 : row group
    const int tc = tid & 15;       // 0..15 : col group

    const int lrow = tid >> 1;          // 0..127
    const int lcol = (tid & 1) * 4;     // 0 or 4

    const float* Ap = A + (long)(m0 + lrow) * K + lcol;
    const float* Bp = B + (long)(n0 + lrow) * K + lcol;

    float acc[8][8];
#pragma unroll
    for (int i = 0; i < 8; i++)
#pragma unroll
        for (int j = 0; j < 8; j++) acc[i][j] = 0.0f;

    for (int k0 = 0; k0 < K; k0 += 8) {
        float4 a = *(const float4*)(Ap + k0);
        float4 b = *(const float4*)(Bp + k0);
        __syncthreads();               // previous tile fully consumed
        As[lcol + 0][lrow] = a.x;
        As[lcol + 1][lrow] = a.y;
        As[lcol + 2][lrow] = a.z;
        As[lcol + 3][lrow] = a.w;
        Bs[lcol + 0][lrow] = b.x;
        Bs[lcol + 1][lrow] = b.y;
        Bs[lcol + 2][lrow] = b.z;
        Bs[lcol + 3][lrow] = b.w;
        __syncthreads();

#pragma unroll
        for (int k = 0; k < 8; k++) {
            float4 a0 = *(const float4*)&As[k][tr * 8];
            float4 a1 = *(const float4*)&As[k][tr * 8 + 4];
            float4 b0 = *(const float4*)&Bs[k][tc * 8];
            float4 b1 = *(const float4*)&Bs[k][tc * 8 + 4];
            float ra[8] = {a0.x, a0.y, a0.z, a0.w, a1.x, a1.y, a1.z, a1.w};
            float rb[8] = {b0.x, b0.y, b0.z, b0.w, b1.x, b1.y, b1.z, b1.w};
#pragma unroll
            for (int i = 0; i < 8; i++)
#pragma unroll
                for (int j = 0; j < 8; j++)
                    acc[i][j] = fmaf(ra[i], rb[j], acc[i][j]);
        }
    }

    float* Cp = C + (long)(m0 + tr * 8) * N + n0 + tc * 8;
#pragma unroll
    for (int i = 0; i < 8; i++) {
        *(float4*)(Cp + (long)i * N)     = make_float4(acc[i][0], acc[i][1], acc[i][2], acc[i][3]);
        *(float4*)(Cp + (long)i * N + 4) = make_float4(acc[i][4], acc[i][5], acc[i][6], acc[i][7]);
    }
}

// =================================================================
// RoPE (in place), folds optional scale (1/sqrt(HD) for Q).
// x: (TOKENS, heads*128). cos/sin: (TOKENS, 128).
// out[d]    = x[d]*cos[d]    - x[d+64]*sin[d]
// out[d+64] = x[d+64]*cos[d+64] + x[d]*sin[d+64]
// =================================================================
__global__ __launch_bounds__(256)
void rope_kernel(float* __restrict__ x, const float* __restrict__ cosb,
                 const float* __restrict__ sinb, int heads, float scale)
{
    long idx = (long)blockIdx.x * blockDim.x + threadIdx.x;
    long total = (long)TOKENS * heads * 64;
    if (idx >= total) return;
    int d = (int)(idx & 63);
    long t2 = idx >> 6;
    int h = (int)(t2 % heads);
    long tok = t2 / heads;
    float* row = x + (tok * heads + h) * HD;
    float c0 = cosb[tok * HD + d];
    float s0 = sinb[tok * HD + d];
    float c1 = cosb[tok * HD + d + 64];
    float s1 = sinb[tok * HD + d + 64];
    float a = row[d];
    float b = row[d + 64];
    row[d]      = (a * c0 - b * s0) * scale;
    row[d + 64] = (b * c1 + a * s1) * scale;
}

// =================================================================
// Flash attention (causal, GQA 4:1), fp32.
// Q: (TOKENS, 4096) [scaled+roped], K/V: (TOKENS, 1024) [K roped].
// O: (TOKENS, 4096).
// grid: (SEQ/64, BATCH*NH). 256 threads.
// smem: Qt[128][64] (d-major), Kt[128][64] (d-major),
//       Vs[64][128] (row-major), Ps[64][64].   Total 112 KB.
// thread (ty=tid/16, tx=tid%16): scores 4(i) x 4(j); output 4(i) x 8(d).
// =================================================================
__global__ __launch_bounds__(256)
void attn_kernel(const float* __restrict__ Q, const float* __restrict__ K,
                 const float* __restrict__ V, float* __restrict__ O)
{
    extern __shared__ float sm[];
    float* Qt = sm;            // 128*64
    float* Kt = Qt + 8192;     // 128*64
    float* Vs = Kt + 8192;     // 64*128
    float* Ps = Vs + 8192;     // 64*64

    const int tid = threadIdx.x;
    const int bh = blockIdx.y;
    const int b   = bh >> 5;           // /32
    const int h   = bh & 31;
    const int kvh = h >> 2;            // GQA group of 4
    const int q0  = blockIdx.x * 64;

    const float* Qb = Q + (long)b * SEQ * QROW + h * HD;
    const float* Kb = K + (long)b * SEQ * KROW + kvh * HD;
    const float* Vb = V + (long)b * SEQ * KROW + kvh * HD;

    // ---- load Q tile transposed (d-major) ----
#pragma unroll
    for (int r = 0; r < 8; r++) {
        int idx = r * 256 + tid;       // 0..2047
        int row = idx & 63;
        int c4  = idx >> 6;            // 0..31
        float4 v = *(const float4*)(Qb + (long)(q0 + row) * QROW + c4 * 4);
        Qt[(c4 * 4 + 0) * 64 + row] = v.x;
        Qt[(c4 * 4 + 1) * 64 + row] = v.y;
        Qt[(c4 * 4 + 2) * 64 + row] = v.z;
        Qt[(c4 * 4 + 3) * 64 + row] = v.w;
    }

    const int ty = tid >> 4;   // 0..15 (i-group of 4)
    const int tx = tid & 15;   // 0..15

    float mrow[4], lrow[4], acc[4][8];
#pragma unroll
    for (int i = 0; i < 4; i++) {
        mrow[i] = -1e30f;
        lrow[i] = 0.0f;
#pragma unroll
        for (int d = 0; d < 8; d++) acc[i][d] = 0.0f;
    }

    const int nkt = (q0 >> 6) + 1;     // causal: key tiles needed

    for (int kt = 0; kt < nkt; kt++) {
        const int k0 = kt * 64;

        // ---- load K tile transposed, V tile row-major ----
#pragma unroll
        for (int r = 0; r < 8; r++) {
            int idx = r * 256 + tid;
            int row = idx & 63;
            int c4  = idx >> 6;
            float4 v = *(const float4*)(Kb + (long)(k0 + row) * KROW + c4 * 4);
            Kt[(c4 * 4 + 0) * 64 + row] = v.x;
            Kt[(c4 * 4 + 1) * 64 + row] = v.y;
            Kt[(c4 * 4 + 2) * 64 + row] = v.z;
            Kt[(c4 * 4 + 3) * 64 + row] = v.w;
        }
#pragma unroll
        for (int r = 0; r < 8; r++) {
            int idx = r * 256 + tid;
            int row = idx >> 5;        // 0..63
            int c4  = idx & 31;
            float4 v = *(const float4*)(Vb + (long)(k0 + row) * KROW + c4 * 4);
            *(float4*)(Vs + row * 128 + c4 * 4) = v;
        }
        __syncthreads();

        // ---- scores S = Q K^T  (4x4 per thread) ----
        float s[4][4];
#pragma unroll
        for (int i = 0; i < 4; i++)
#pragma unroll
            for (int j = 0; j < 4; j++) s[i][j] = 0.0f;

#pragma unroll 8
        for (int d = 0; d < 128; d++) {
            float4 q4 = *(const float4*)(Qt + d * 64 + ty * 4);
            float4 k4 = *(const float4*)(Kt + d * 64 + tx * 4);
            float rq[4] = {q4.x, q4.y, q4.z, q4.w};
            float rk[4] = {k4.x, k4.y, k4.z, k4.w};
#pragma unroll
            for (int i = 0; i < 4; i++)
#pragma unroll
                for (int j = 0; j < 4; j++)
                    s[i][j] = fmaf(rq[i], rk[j], s[i][j]);
        }

        // ---- causal mask (diagonal tile only) ----
        if (kt == nkt - 1) {
#pragma unroll
            for (int i = 0; i < 4; i++) {
                int qi = q0 + ty * 4 + i;
#pragma unroll
                for (int j = 0; j < 4; j++) {
                    int kj = k0 + tx * 4 + j;
                    if (kj > qi) s[i][j] = -1e30f;
                }
            }
        }

        // ---- online softmax update (row reductions across 16-lane group) ----
#pragma unroll
        for (int i = 0; i < 4; i++) {
            float mx = fmaxf(fmaxf(s[i][0], s[i][1]), fmaxf(s[i][2], s[i][3]));
#pragma unroll
            for (int w = 8; w >= 1; w >>= 1)
                mx = fmaxf(mx, __shfl_xor_sync(0xffffffffu, mx, w));
            float mnew = fmaxf(mrow[i], mx);
            float corr = __expf(mrow[i] - mnew);
            float p0 = __expf(s[i][0] - mnew);
            float p1 = __expf(s[i][1] - mnew);
            float p2 = __expf(s[i][2] - mnew);
            float p3 = __expf(s[i][3] - mnew);
            float rs = p0 + p1 + p2 + p3;
#pragma unroll
            for (int w = 8; w >= 1; w >>= 1)
                rs += __shfl_xor_sync(0xffffffffu, rs, w);
            lrow[i] = lrow[i] * corr + rs;
            mrow[i] = mnew;
#pragma unroll
            for (int d = 0; d < 8; d++) acc[i][d] *= corr;
            *(float4*)(Ps + (ty * 4 + i) * 64 + tx * 4) = make_float4(p0, p1, p2, p3);
        }
        __syncthreads();

        // ---- O += P V  (4x8 per thread) ----
#pragma unroll 8
        for (int j = 0; j < 64; j++) {
            float p0 = Ps[(ty * 4 + 0) * 64 + j];
            float p1 = Ps[(ty * 4 + 1) * 64 + j];
            float p2 = Ps[(ty * 4 + 2) * 64 + j];
            float p3 = Ps[(ty * 4 + 3) * 64 + j];
            float4 va = *(const float4*)(Vs + j * 128 + tx * 8);
            float4 vb = *(const float4*)(Vs + j * 128 + tx * 8 + 4);
            float rv[8] = {va.x, va.y, va.z, va.w, vb.x, vb.y, vb.z, vb.w};
            float rp[4] = {p0, p1, p2, p3};
#pragma unroll
            for (int i = 0; i < 4; i++)
#pragma unroll
                for (int d = 0; d < 8; d++)
                    acc[i][d] = fmaf(rp[i], rv[d], acc[i][d]);
        }
        __syncthreads();   // before next tile overwrites Kt/Vs
    }

    // ---- epilogue: O / l ----
#pragma unroll
    for (int i = 0; i < 4; i++) {
        float inv = 1.0f / lrow[i];
        long orow = (long)(b * SEQ + q0 + ty * 4 + i) * QROW + h * HD + tx * 8;
        *(float4*)(O + orow)     = make_float4(acc[i][0] * inv, acc[i][1] * inv,
                                               acc[i][2] * inv, acc[i][3] * inv);
        *(float4*)(O + orow + 4) = make_float4(acc[i][4] * inv, acc[i][5] * inv,
                                               acc[i][6] * inv, acc[i][7] * inv);
    }
}

// =================================================================
extern "C" void kernel_launch(void* const* d_in, const int* in_sizes, int n_in,
                              void* d_out, int out_size)
{
    const float* hs   = (const float*)d_in[0];
    const float* cosb = (const float*)d_in[1];
    const float* sinb = (const float*)d_in[2];
    const float* wq   = (const float*)d_in[3];
    const float* wk   = (const float*)d_in[4];
    const float* wv   = (const float*)d_in[5];
    const float* wo   = (const float*)d_in[6];
    float* out = (float*)d_out;

    float *q, *k, *v, *attn;
    cudaGetSymbolAddress((void**)&q,    g_q);
    cudaGetSymbolAddress((void**)&k,    g_k);
    cudaGetSymbolAddress((void**)&v,    g_v);
    cudaGetSymbolAddress((void**)&attn, g_attn);

    // QKV projections
    gemm_nt<<<dim3(QROW / 128, TOKENS / 128), 256>>>(hs, wq, q, TOKENS, QROW, HID);
    gemm_nt<<<dim3(KROW / 128, TOKENS / 128), 256>>>(hs, wk, k, TOKENS, KROW, HID);
    gemm_nt<<<dim3(KROW / 128, TOKENS / 128), 256>>>(hs, wv, v, TOKENS, KROW, HID);

    // RoPE (scale 1/sqrt(128) folded into Q)
    const float scaling = 0.08838834764831845f;
    rope_kernel<<<(TOKENS * NH  * 64) / 256, 256>>>(q, cosb, sinb, NH,  scaling);
    rope_kernel<<<(TOKENS * NKV * 64) / 256, 256>>>(k, cosb, sinb, NKV, 1.0f);

    // Flash attention
    cudaFuncSetAttribute(attn_kernel, cudaFuncAttributeMaxDynamicSharedMemorySize, 114688);
    attn_kernel<<<dim3(SEQ / 64, BATCH * NH), 256, 114688>>>(q, k, v, attn);

    // Output projection -> d_out
    gemm_nt<<<dim3(HID / 128, TOKENS / 128), 256>>>(attn, wo, out, TOKENS, HID, QROW);
}

// round 3
// speedup vs baseline: 2.2999x; 2.2999x over previous
#include <cuda_runtime.h>
#include <cuda_bf16.h>
#include <math.h>
#include <cstdint>

// Problem constants
#define BATCH 2
#define SEQ   2048
#define HID   4096
#define NH    32
#define NKV   8
#define HD    128
#define TOKENS (BATCH*SEQ)          // 4096
#define QROW (NH*HD)                // 4096
#define KROW (NKV*HD)               // 1024

// ---------------- scratch (no cudaMalloc allowed) ----------------
__device__ float g_q[(size_t)TOKENS * QROW];     // 64 MB
__device__ float g_k[(size_t)TOKENS * KROW];     // 16 MB
__device__ float g_v[(size_t)TOKENS * KROW];     // 16 MB
__device__ float g_attn[(size_t)TOKENS * QROW];  // 64 MB
// tf32-rounded operand copies
__device__ float g_hsc[(size_t)TOKENS * HID];    // 64 MB
__device__ float g_wqc[(size_t)QROW * HID];      // 64 MB
__device__ float g_wkc[(size_t)KROW * HID];      // 16 MB
__device__ float g_wvc[(size_t)KROW * HID];      // 16 MB
__device__ float g_woc[(size_t)HID * QROW];      // 64 MB

// ---------------- helpers ----------------
__device__ __forceinline__ uint32_t sa(const void* p) {
    return (uint32_t)__cvta_generic_to_shared(p);
}
__device__ __forceinline__ void cp_async16(uint32_t s, const void* g) {
    asm volatile("cp.async.cg.shared.global [%0], [%1], 16;" :: "r"(s), "l"(g));
}
__device__ __forceinline__ void cp_commit() {
    asm volatile("cp.async.commit_group;" ::: "memory");
}
template <int N>
__device__ __forceinline__ void cp_wait() {
    asm volatile("cp.async.wait_group %0;" :: "n"(N) : "memory");
}

__device__ __forceinline__ void mma_tf32(float* d, const uint32_t* a, const uint32_t* b) {
    asm volatile(
        "mma.sync.aligned.m16n8k8.row.col.f32.tf32.tf32.f32 "
        "{%0,%1,%2,%3}, {%4,%5,%6,%7}, {%8,%9}, {%0,%1,%2,%3};"
        : "+f"(d[0]), "+f"(d[1]), "+f"(d[2]), "+f"(d[3])
        : "r"(a[0]), "r"(a[1]), "r"(a[2]), "r"(a[3]), "r"(b[0]), "r"(b[1]));
}

// =================================================================
// tf32 round-to-nearest conversion (elementwise, float4)
// =================================================================
__global__ __launch_bounds__(256)
void tf32_round_kernel(const float4* __restrict__ in, float4* __restrict__ out, long n4)
{
    long i = (long)blockIdx.x * blockDim.x + threadIdx.x;
    if (i >= n4) return;
    float4 v = in[i];
    uint32_t a, b, c, d;
    asm("cvt.rn.tf32.f32 %0, %1;" : "=r"(a) : "f"(v.x));
    asm("cvt.rn.tf32.f32 %0, %1;" : "=r"(b) : "f"(v.y));
    asm("cvt.rn.tf32.f32 %0, %1;" : "=r"(c) : "f"(v.z));
    asm("cvt.rn.tf32.f32 %0, %1;" : "=r"(d) : "f"(v.w));
    out[i] = make_float4(__uint_as_float(a), __uint_as_float(b),
                         __uint_as_float(c), __uint_as_float(d));
}

// =================================================================
// tf32 mma.sync GEMM:  C[m,n] = sum_k A[m,k]*B[n,k]
// A: MxK row-major, B: NxK row-major (both pre-rounded to tf32).
// Block tile 128(M) x 256(N), BK=32. 8 warps, warp tile 64x64.
// Double-buffered cp.async. M%128==0, N%256==0, K%32==0.
// =================================================================
#define GSTRIDE 36                       // smem row stride in floats
#define A_FLOATS (128 * GSTRIDE)         // 4608
#define B_FLOATS (256 * GSTRIDE)         // 9216
#define STAGE_FLOATS (A_FLOATS + B_FLOATS)
#define GEMM_SMEM (2 * STAGE_FLOATS * 4) // 110592 bytes

__global__ __launch_bounds__(256, 1)
void gemm_mma(const float* __restrict__ A, const float* __restrict__ B,
              float* __restrict__ C, int M, int N, int K)
{
    extern __shared__ float sm[];

    const int tid = threadIdx.x;
    const int wid = tid >> 5;
    const int lane = tid & 31;
    const int g = lane >> 2;         // group 0..7
    const int t = lane & 3;          // 0..3
    const int wm = wid & 1;          // warp m index (2)
    const int wn = wid >> 1;         // warp n index (4)
    const int m0 = blockIdx.y * 128;
    const int n0 = blockIdx.x * 256;

    const float* Ag = A + (size_t)m0 * K;
    const float* Bg = B + (size_t)n0 * K;

    // ---- stage loader ----
    auto load_stage = [&](int kt, int st) {
        float* As = sm + st * STAGE_FLOATS;
        float* Bs = As + A_FLOATS;
        const float* ap = Ag + kt * 32;
        const float* bp = Bg + kt * 32;
#pragma unroll
        for (int r = 0; r < 4; r++) {           // A: 1024 float4 chunks
            int c = r * 256 + tid;
            int row = c >> 3;
            int c4  = (c & 7) * 4;
            cp_async16(sa(As + row * GSTRIDE + c4), ap + (size_t)row * K + c4);
        }
#pragma unroll
        for (int r = 0; r < 8; r++) {           // B: 2048 float4 chunks
            int c = r * 256 + tid;
            int row = c >> 3;
            int c4  = (c & 7) * 4;
            cp_async16(sa(Bs + row * GSTRIDE + c4), bp + (size_t)row * K + c4);
        }
        cp_commit();
    };

    float d[4][8][4];
#pragma unroll
    for (int mi = 0; mi < 4; mi++)
#pragma unroll
        for (int ni = 0; ni < 8; ni++)
#pragma unroll
            for (int r = 0; r < 4; r++) d[mi][ni][r] = 0.0f;

    const int NT = K / 32;
    load_stage(0, 0);

    for (int kt = 0; kt < NT; kt++) {
        const int st = kt & 1;
        if (kt + 1 < NT) { load_stage(kt + 1, st ^ 1); cp_wait<1>(); }
        else             { cp_wait<0>(); }
        __syncthreads();

        const float* As = sm + st * STAGE_FLOATS;
        const float* Bs = As + A_FLOATS;

#pragma unroll
        for (int kk = 0; kk < 4; kk++) {
            uint32_t a[4][4], b[8][2];
#pragma unroll
            for (int mi = 0; mi < 4; mi++) {
                const float* ap = As + (wm * 64 + mi * 16 + g) * GSTRIDE + kk * 8 + t;
                a[mi][0] = __float_as_uint(ap[0]);
                a[mi][1] = __float_as_uint(ap[8 * GSTRIDE]);
                a[mi][2] = __float_as_uint(ap[4]);
                a[mi][3] = __float_as_uint(ap[8 * GSTRIDE + 4]);
            }
#pragma unroll
            for (int ni = 0; ni < 8; ni++) {
                const float* bp = Bs + (wn * 64 + ni * 8 + g) * GSTRIDE + kk * 8 + t;
                b[ni][0] = __float_as_uint(bp[0]);
                b[ni][1] = __float_as_uint(bp[4]);
            }
#pragma unroll
            for (int mi = 0; mi < 4; mi++)
#pragma unroll
                for (int ni = 0; ni < 8; ni++)
                    mma_tf32(d[mi][ni], a[mi], b[ni]);
        }
        __syncthreads();
    }

    // ---- epilogue ----
#pragma unroll
    for (int mi = 0; mi < 4; mi++) {
        const int r0 = m0 + wm * 64 + mi * 16 + g;
        float* c0p = C + (size_t)r0 * N + n0 + wn * 64;
        float* c1p = c0p + (size_t)8 * N;
#pragma unroll
        for (int ni = 0; ni < 8; ni++) {
            *(float2*)(c0p + ni * 8 + t * 2) = make_float2(d[mi][ni][0], d[mi][ni][1]);
            *(float2*)(c1p + ni * 8 + t * 2) = make_float2(d[mi][ni][2], d[mi][ni][3]);
        }
    }
}

// =================================================================
// RoPE (in place), folds optional scale (1/sqrt(HD) for Q).
// =================================================================
__global__ __launch_bounds__(256)
void rope_kernel(float* __restrict__ x, const float* __restrict__ cosb,
                 const float* __restrict__ sinb, int heads, float scale)
{
    long idx = (long)blockIdx.x * blockDim.x + threadIdx.x;
    long total = (long)TOKENS * heads * 64;
    if (idx >= total) return;
    int d = (int)(idx & 63);
    long t2 = idx >> 6;
    int h = (int)(t2 % heads);
    long tok = t2 / heads;
    float* row = x + (tok * heads + h) * HD;
    float c0 = cosb[tok * HD + d];
    float s0 = sinb[tok * HD + d];
    float c1 = cosb[tok * HD + d + 64];
    float s1 = sinb[tok * HD + d + 64];
    float a = row[d];
    float b = row[d + 64];
    row[d]      = (a * c0 - b * s0) * scale;
    row[d + 64] = (b * c1 + a * s1) * scale;
}

// =================================================================
// Flash attention (causal, GQA 4:1), fp32 SIMT (R1 version, passing).
// =================================================================
__global__ __launch_bounds__(256)
void attn_kernel(const float* __restrict__ Q, const float* __restrict__ K,
                 const float* __restrict__ V, float* __restrict__ O)
{
    extern __shared__ float sm[];
    float* Qt = sm;            // 128*64
    float* Kt = Qt + 8192;     // 128*64
    float* Vs = Kt + 8192;     // 64*128
    float* Ps = Vs + 8192;     // 64*64

    const int tid = threadIdx.x;
    const int bh = blockIdx.y;
    const int b   = bh >> 5;
    const int h   = bh & 31;
    const int kvh = h >> 2;
    const int q0  = blockIdx.x * 64;

    const float* Qb = Q + (long)b * SEQ * QROW + h * HD;
    const float* Kb = K + (long)b * SEQ * KROW + kvh * HD;
    const float* Vb = V + (long)b * SEQ * KROW + kvh * HD;

#pragma unroll
    for (int r = 0; r < 8; r++) {
        int idx = r * 256 + tid;
        int row = idx & 63;
        int c4  = idx >> 6;
        float4 v = *(const float4*)(Qb + (long)(q0 + row) * QROW + c4 * 4);
        Qt[(c4 * 4 + 0) * 64 + row] = v.x;
        Qt[(c4 * 4 + 1) * 64 + row] = v.y;
        Qt[(c4 * 4 + 2) * 64 + row] = v.z;
        Qt[(c4 * 4 + 3) * 64 + row] = v.w;
    }

    const int ty = tid >> 4;
    const int tx = tid & 15;

    float mrow[4], lrow[4], acc[4][8];
#pragma unroll
    for (int i = 0; i < 4; i++) {
        mrow[i] = -1e30f;
        lrow[i] = 0.0f;
#pragma unroll
        for (int d = 0; d < 8; d++) acc[i][d] = 0.0f;
    }

    const int nkt = (q0 >> 6) + 1;

    for (int kt = 0; kt < nkt; kt++) {
        const int k0 = kt * 64;

#pragma unroll
        for (int r = 0; r < 8; r++) {
            int idx = r * 256 + tid;
            int row = idx & 63;
            int c4  = idx >> 6;
            float4 v = *(const float4*)(Kb + (long)(k0 + row) * KROW + c4 * 4);
            Kt[(c4 * 4 + 0) * 64 + row] = v.x;
            Kt[(c4 * 4 + 1) * 64 + row] = v.y;
            Kt[(c4 * 4 + 2) * 64 + row] = v.z;
            Kt[(c4 * 4 + 3) * 64 + row] = v.w;
        }
#pragma unroll
        for (int r = 0; r < 8; r++) {
            int idx = r * 256 + tid;
            int row = idx >> 5;
            int c4  = idx & 31;
            float4 v = *(const float4*)(Vb + (long)(k0 + row) * KROW + c4 * 4);
            *(float4*)(Vs + row * 128 + c4 * 4) = v;
        }
        __syncthreads();

        float s[4][4];
#pragma unroll
        for (int i = 0; i < 4; i++)
#pragma unroll
            for (int j = 0; j < 4; j++) s[i][j] = 0.0f;

#pragma unroll 8
        for (int d = 0; d < 128; d++) {
            float4 q4 = *(const float4*)(Qt + d * 64 + ty * 4);
            float4 k4 = *(const float4*)(Kt + d * 64 + tx * 4);
            float rq[4] = {q4.x, q4.y, q4.z, q4.w};
            float rk[4] = {k4.x, k4.y, k4.z, k4.w};
#pragma unroll
            for (int i = 0; i < 4; i++)
#pragma unroll
                for (int j = 0; j < 4; j++)
                    s[i][j] = fmaf(rq[i], rk[j], s[i][j]);
        }

        if (kt == nkt - 1) {
#pragma unroll
            for (int i = 0; i < 4; i++) {
                int qi = q0 + ty * 4 + i;
#pragma unroll
                for (int j = 0; j < 4; j++) {
                    int kj = k0 + tx * 4 + j;
                    if (kj > qi) s[i][j] = -1e30f;
                }
            }
        }

#pragma unroll
        for (int i = 0; i < 4; i++) {
            float mx = fmaxf(fmaxf(s[i][0], s[i][1]), fmaxf(s[i][2], s[i][3]));
#pragma unroll
            for (int w = 8; w >= 1; w >>= 1)
                mx = fmaxf(mx, __shfl_xor_sync(0xffffffffu, mx, w));
            float mnew = fmaxf(mrow[i], mx);
            float corr = __expf(mrow[i] - mnew);
            float p0 = __expf(s[i][0] - mnew);
            float p1 = __expf(s[i][1] - mnew);
            float p2 = __expf(s[i][2] - mnew);
            float p3 = __expf(s[i][3] - mnew);
            float rs = p0 + p1 + p2 + p3;
#pragma unroll
            for (int w = 8; w >= 1; w >>= 1)
                rs += __shfl_xor_sync(0xffffffffu, rs, w);
            lrow[i] = lrow[i] * corr + rs;
            mrow[i] = mnew;
#pragma unroll
            for (int d = 0; d < 8; d++) acc[i][d] *= corr;
            *(float4*)(Ps + (ty * 4 + i) * 64 + tx * 4) = make_float4(p0, p1, p2, p3);
        }
        __syncthreads();

#pragma unroll 8
        for (int j = 0; j < 64; j++) {
            float p0 = Ps[(ty * 4 + 0) * 64 + j];
            float p1 = Ps[(ty * 4 + 1) * 64 + j];
            float p2 = Ps[(ty * 4 + 2) * 64 + j];
            float p3 = Ps[(ty * 4 + 3) * 64 + j];
            float4 va = *(const float4*)(Vs + j * 128 + tx * 8);
            float4 vb = *(const float4*)(Vs + j * 128 + tx * 8 + 4);
            float rv[8] = {va.x, va.y, va.z, va.w, vb.x, vb.y, vb.z, vb.w};
            float rp[4] = {p0, p1, p2, p3};
#pragma unroll
            for (int i = 0; i < 4; i++)
#pragma unroll
                for (int d = 0; d < 8; d++)
                    acc[i][d] = fmaf(rp[i], rv[d], acc[i][d]);
        }
        __syncthreads();
    }

#pragma unroll
    for (int i = 0; i < 4; i++) {
        float inv = 1.0f / lrow[i];
        long orow = (long)(b * SEQ + q0 + ty * 4 + i) * QROW + h * HD + tx * 8;
        *(float4*)(O + orow)     = make_float4(acc[i][0] * inv, acc[i][1] * inv,
                                               acc[i][2] * inv, acc[i][3] * inv);
        *(float4*)(O + orow + 4) = make_float4(acc[i][4] * inv, acc[i][5] * inv,
                                               acc[i][6] * inv, acc[i][7] * inv);
    }
}

// =================================================================
extern "C" void kernel_launch(void* const* d_in, const int* in_sizes, int n_in,
                              void* d_out, int out_size)
{
    const float* hs   = (const float*)d_in[0];
    const float* cosb = (const float*)d_in[1];
    const float* sinb = (const float*)d_in[2];
    const float* wq   = (const float*)d_in[3];
    const float* wk   = (const float*)d_in[4];
    const float* wv   = (const float*)d_in[5];
    const float* wo   = (const float*)d_in[6];
    float* out = (float*)d_out;

    float *q, *k, *v, *attn, *hsc, *wqc, *wkc, *wvc, *woc;
    cudaGetSymbolAddress((void**)&q,    g_q);
    cudaGetSymbolAddress((void**)&k,    g_k);
    cudaGetSymbolAddress((void**)&v,    g_v);
    cudaGetSymbolAddress((void**)&attn, g_attn);
    cudaGetSymbolAddress((void**)&hsc,  g_hsc);
    cudaGetSymbolAddress((void**)&wqc,  g_wqc);
    cudaGetSymbolAddress((void**)&wkc,  g_wkc);
    cudaGetSymbolAddress((void**)&wvc,  g_wvc);
    cudaGetSymbolAddress((void**)&woc,  g_woc);

    cudaFuncSetAttribute(attn_kernel, cudaFuncAttributeMaxDynamicSharedMemorySize, 114688);
    cudaFuncSetAttribute(gemm_mma, cudaFuncAttributeMaxDynamicSharedMemorySize, GEMM_SMEM);

    // tf32 RN pre-rounding of all GEMM operands
    const long nHS = (long)TOKENS * HID / 4;
    const long nWQ = (long)QROW * HID / 4;
    const long nWK = (long)KROW * HID / 4;
    tf32_round_kernel<<<(nHS + 255) / 256, 256>>>((const float4*)hs, (float4*)hsc, nHS);
    tf32_round_kernel<<<(nWQ + 255) / 256, 256>>>((const float4*)wq, (float4*)wqc, nWQ);
    tf32_round_kernel<<<(nWK + 255) / 256, 256>>>((const float4*)wk, (float4*)wkc, nWK);
    tf32_round_kernel<<<(nWK + 255) / 256, 256>>>((const float4*)wv, (float4*)wvc, nWK);
    tf32_round_kernel<<<(nWQ + 255) / 256, 256>>>((const float4*)wo, (float4*)woc, nWQ);

    // QKV projections (tf32 mma.sync)
    gemm_mma<<<dim3(QROW / 256, TOKENS / 128), 256, GEMM_SMEM>>>(hsc, wqc, q, TOKENS, QROW, HID);
    gemm_mma<<<dim3(KROW / 256, TOKENS / 128), 256, GEMM_SMEM>>>(hsc, wkc, k, TOKENS, KROW, HID);
    gemm_mma<<<dim3(KROW / 256, TOKENS / 128), 256, GEMM_SMEM>>>(hsc, wvc, v, TOKENS, KROW, HID);

    // RoPE (scale 1/sqrt(128) folded into Q)
    const float scaling = 0.08838834764831845f;
    rope_kernel<<<(TOKENS * NH  * 64) / 256, 256>>>(q, cosb, sinb, NH,  scaling);
    rope_kernel<<<(TOKENS * NKV * 64) / 256, 256>>>(k, cosb, sinb, NKV, 1.0f);

    // Flash attention (fp32 SIMT)
    attn_kernel<<<dim3(SEQ / 64, BATCH * NH), 256, 114688>>>(q, k, v, attn);

    // Round attention output to tf32 (in place), then output projection
    const long nAT = (long)TOKENS * QROW / 4;
    tf32_round_kernel<<<(nAT + 255) / 256, 256>>>((const float4*)attn, (float4*)attn, nAT);
    gemm_mma<<<dim3(HID / 256, TOKENS / 128), 256, GEMM_SMEM>>>(attn, woc, out, TOKENS, HID, QROW);
}

// round 4
// speedup vs baseline: 3.5312x; 1.5354x over previous
#include <cuda_runtime.h>
#include <cuda_bf16.h>
#include <math.h>
#include <cstdint>

// Problem constants
#define BATCH 2
#define SEQ   2048
#define HID   4096
#define NH    32
#define NKV   8
#define HD    128
#define TOKENS (BATCH*SEQ)          // 4096
#define QROW (NH*HD)                // 4096
#define KROW (NKV*HD)               // 1024

// ---------------- scratch (no cudaMalloc allowed) ----------------
__device__ float g_q[(size_t)TOKENS * QROW];     // 64 MB
__device__ float g_k[(size_t)TOKENS * KROW];     // 16 MB
__device__ float g_v[(size_t)TOKENS * KROW];     // 16 MB
__device__ float g_attn[(size_t)TOKENS * QROW];  // 64 MB
// tf32-rounded operand copies
__device__ float g_hsc[(size_t)TOKENS * HID];    // 64 MB
__device__ float g_wqc[(size_t)QROW * HID];      // 64 MB
__device__ float g_wkc[(size_t)KROW * HID];      // 16 MB
__device__ float g_wvc[(size_t)KROW * HID];      // 16 MB
__device__ float g_woc[(size_t)HID * QROW];      // 64 MB

// ---------------- helpers ----------------
__device__ __forceinline__ uint32_t sa(const void* p) {
    return (uint32_t)__cvta_generic_to_shared(p);
}
__device__ __forceinline__ void cp_async16(uint32_t s, const void* g) {
    asm volatile("cp.async.cg.shared.global [%0], [%1], 16;" :: "r"(s), "l"(g));
}
__device__ __forceinline__ void cp_commit() {
    asm volatile("cp.async.commit_group;" ::: "memory");
}
template <int N>
__device__ __forceinline__ void cp_wait() {
    asm volatile("cp.async.wait_group %0;" :: "n"(N) : "memory");
}

__device__ __forceinline__ void mma_tf32(float* d, const uint32_t* a, const uint32_t* b) {
    asm volatile(
        "mma.sync.aligned.m16n8k8.row.col.f32.tf32.tf32.f32 "
        "{%0,%1,%2,%3}, {%4,%5,%6,%7}, {%8,%9}, {%0,%1,%2,%3};"
        : "+f"(d[0]), "+f"(d[1]), "+f"(d[2]), "+f"(d[3])
        : "r"(a[0]), "r"(a[1]), "r"(a[2]), "r"(a[3]), "r"(b[0]), "r"(b[1]));
}

__device__ __forceinline__ float tf32rn(float x) {
    uint32_t u;
    asm("cvt.rn.tf32.f32 %0, %1;" : "=r"(u) : "f"(x));
    return __uint_as_float(u);
}

// fast 2^x via FMA polynomial (avoids MUFU bottleneck; rel err ~1.5e-5)
__device__ __forceinline__ float exp2p(float x) {
    x = fmaxf(x, -126.0f);
    int   i = __float2int_rd(x);
    float f = x - (float)i;
    float p = 1.54035303934e-4f;
    p = fmaf(p, f, 1.33335581464e-3f);
    p = fmaf(p, f, 9.61812910763e-3f);
    p = fmaf(p, f, 5.55041086648e-2f);
    p = fmaf(p, f, 2.40226506959e-1f);
    p = fmaf(p, f, 6.93147180560e-1f);
    p = fmaf(p, f, 1.0f);
    return __int_as_float((i + 127) << 23) * p;
}

// =================================================================
// tf32 round-to-nearest conversion (elementwise, float4)
// =================================================================
__global__ __launch_bounds__(256)
void tf32_round_kernel(const float4* __restrict__ in, float4* __restrict__ out, long n4)
{
    long i = (long)blockIdx.x * blockDim.x + threadIdx.x;
    if (i >= n4) return;
    float4 v = in[i];
    out[i] = make_float4(tf32rn(v.x), tf32rn(v.y), tf32rn(v.z), tf32rn(v.w));
}

// =================================================================
// tf32 mma.sync GEMM:  C[m,n] = sum_k A[m,k]*B[n,k]   (from R3, passing)
// =================================================================
#define GSTRIDE 36
#define A_FLOATS (128 * GSTRIDE)
#define B_FLOATS (256 * GSTRIDE)
#define STAGE_FLOATS (A_FLOATS + B_FLOATS)
#define GEMM_SMEM (2 * STAGE_FLOATS * 4)

__global__ __launch_bounds__(256, 1)
void gemm_mma(const float* __restrict__ A, const float* __restrict__ B,
              float* __restrict__ C, int M, int N, int K)
{
    extern __shared__ float sm[];

    const int tid = threadIdx.x;
    const int wid = tid >> 5;
    const int lane = tid & 31;
    const int g = lane >> 2;
    const int t = lane & 3;
    const int wm = wid & 1;
    const int wn = wid >> 1;
    const int m0 = blockIdx.y * 128;
    const int n0 = blockIdx.x * 256;

    const float* Ag = A + (size_t)m0 * K;
    const float* Bg = B + (size_t)n0 * K;

    auto load_stage = [&](int kt, int st) {
        float* As = sm + st * STAGE_FLOATS;
        float* Bs = As + A_FLOATS;
        const float* ap = Ag + kt * 32;
        const float* bp = Bg + kt * 32;
#pragma unroll
        for (int r = 0; r < 4; r++) {
            int c = r * 256 + tid;
            int row = c >> 3;
            int c4  = (c & 7) * 4;
            cp_async16(sa(As + row * GSTRIDE + c4), ap + (size_t)row * K + c4);
        }
#pragma unroll
        for (int r = 0; r < 8; r++) {
            int c = r * 256 + tid;
            int row = c >> 3;
            int c4  = (c & 7) * 4;
            cp_async16(sa(Bs + row * GSTRIDE + c4), bp + (size_t)row * K + c4);
        }
        cp_commit();
    };

    float d[4][8][4];
#pragma unroll
    for (int mi = 0; mi < 4; mi++)
#pragma unroll
        for (int ni = 0; ni < 8; ni++)
#pragma unroll
            for (int r = 0; r < 4; r++) d[mi][ni][r] = 0.0f;

    const int NT = K / 32;
    load_stage(0, 0);

    for (int kt = 0; kt < NT; kt++) {
        const int st = kt & 1;
        if (kt + 1 < NT) { load_stage(kt + 1, st ^ 1); cp_wait<1>(); }
        else             { cp_wait<0>(); }
        __syncthreads();

        const float* As = sm + st * STAGE_FLOATS;
        const float* Bs = As + A_FLOATS;

#pragma unroll
        for (int kk = 0; kk < 4; kk++) {
            uint32_t a[4][4], b[8][2];
#pragma unroll
            for (int mi = 0; mi < 4; mi++) {
                const float* ap = As + (wm * 64 + mi * 16 + g) * GSTRIDE + kk * 8 + t;
                a[mi][0] = __float_as_uint(ap[0]);
                a[mi][1] = __float_as_uint(ap[8 * GSTRIDE]);
                a[mi][2] = __float_as_uint(ap[4]);
                a[mi][3] = __float_as_uint(ap[8 * GSTRIDE + 4]);
            }
#pragma unroll
            for (int ni = 0; ni < 8; ni++) {
                const float* bp = Bs + (wn * 64 + ni * 8 + g) * GSTRIDE + kk * 8 + t;
                b[ni][0] = __float_as_uint(bp[0]);
                b[ni][1] = __float_as_uint(bp[4]);
            }
#pragma unroll
            for (int mi = 0; mi < 4; mi++)
#pragma unroll
                for (int ni = 0; ni < 8; ni++)
                    mma_tf32(d[mi][ni], a[mi], b[ni]);
        }
        __syncthreads();
    }

#pragma unroll
    for (int mi = 0; mi < 4; mi++) {
        const int r0 = m0 + wm * 64 + mi * 16 + g;
        float* c0p = C + (size_t)r0 * N + n0 + wn * 64;
        float* c1p = c0p + (size_t)8 * N;
#pragma unroll
        for (int ni = 0; ni < 8; ni++) {
            *(float2*)(c0p + ni * 8 + t * 2) = make_float2(d[mi][ni][0], d[mi][ni][1]);
            *(float2*)(c1p + ni * 8 + t * 2) = make_float2(d[mi][ni][2], d[mi][ni][3]);
        }
    }
}

// =================================================================
// RoPE (in place), folds optional scale into Q.
// =================================================================
__global__ __launch_bounds__(256)
void rope_kernel(float* __restrict__ x, const float* __restrict__ cosb,
                 const float* __restrict__ sinb, int heads, float scale)
{
    long idx = (long)blockIdx.x * blockDim.x + threadIdx.x;
    long total = (long)TOKENS * heads * 64;
    if (idx >= total) return;
    int d = (int)(idx & 63);
    long t2 = idx >> 6;
    int h = (int)(t2 % heads);
    long tok = t2 / heads;
    float* row = x + (tok * heads + h) * HD;
    float c0 = cosb[tok * HD + d];
    float s0 = sinb[tok * HD + d];
    float c1 = cosb[tok * HD + d + 64];
    float s1 = sinb[tok * HD + d + 64];
    float a = row[d];
    float b = row[d + 64];
    row[d]      = (a * c0 - b * s0) * scale;
    row[d + 64] = (b * c1 + a * s1) * scale;
}

// =================================================================
// Tensor-core flash attention (causal, GQA 4:1), tf32 mma.sync.
// Q pre-scaled by (1/sqrt(128))*log2(e); probs use 2^x.
// CTA: 128 queries x 1 head. 8 warps, each 16 query rows, all keys.
// Key tile = 64. Smem: Qs[128][132], Ks[64][132], Vt[128][68], Ps[128][68].
// =================================================================
#define AQS 132
#define AVS 68
#define ATTN_SMEM ((128*AQS + 64*AQS + 128*AVS + 128*AVS) * 4)  // 171008 B

__global__ __launch_bounds__(256, 1)
void attn_mma(const float* __restrict__ Q, const float* __restrict__ K,
              const float* __restrict__ V, float* __restrict__ O)
{
    extern __shared__ float sm[];
    float* Qs = sm;                       // 128*132
    float* Ks = Qs + 128 * AQS;           // 64*132
    float* Vt = Ks + 64 * AQS;            // 128*68 (dim-major)
    float* Ps = Vt + 128 * AVS;           // 128*68

    const int tid = threadIdx.x;
    const int wid = tid >> 5;
    const int lane = tid & 31;
    const int g = lane >> 2;
    const int t = lane & 3;

    const int bh = blockIdx.y;
    const int b   = bh >> 5;
    const int h   = bh & 31;
    const int kvh = h >> 2;
    const int qt  = (int)(gridDim.x - 1 - blockIdx.x);
    const int q0  = qt * 128;

    const float* Qb = Q + (size_t)b * SEQ * QROW + h * HD;
    const float* Kb = K + (size_t)b * SEQ * KROW + kvh * HD;
    const float* Vb = V + (size_t)b * SEQ * KROW + kvh * HD;

    // ---- load Q tile (tf32-rounded) ----
#pragma unroll
    for (int it = 0; it < 16; it++) {
        int idx = it * 256 + tid;            // 0..4095
        int row = idx >> 5;
        int c4  = (idx & 31) * 4;
        float4 v = *(const float4*)(Qb + (size_t)(q0 + row) * QROW + c4);
        *(float4*)(Qs + row * AQS + c4) =
            make_float4(tf32rn(v.x), tf32rn(v.y), tf32rn(v.z), tf32rn(v.w));
    }

    const int qbase = q0 + wid * 16;       // this warp's first query row

    float m0r = -1e30f, m1r = -1e30f, l0r = 0.0f, l1r = 0.0f;
    float oa[16][4];
#pragma unroll
    for (int ni = 0; ni < 16; ni++)
#pragma unroll
        for (int r = 0; r < 4; r++) oa[ni][r] = 0.0f;

    const int nkt = qt * 2 + 2;            // causal key tiles

    for (int kt = 0; kt < nkt; kt++) {
        const int k0 = kt * 64;

        // ---- load K tile (row-major, stride AQS) ----
#pragma unroll
        for (int it = 0; it < 8; it++) {
            int idx = it * 256 + tid;        // 0..2047
            int row = idx >> 5;
            int c4  = (idx & 31) * 4;
            float4 v = *(const float4*)(Kb + (size_t)(k0 + row) * KROW + c4);
            *(float4*)(Ks + row * AQS + c4) =
                make_float4(tf32rn(v.x), tf32rn(v.y), tf32rn(v.z), tf32rn(v.w));
        }
        // ---- load V tile transposed (dim-major, stride AVS) ----
#pragma unroll
        for (int it = 0; it < 8; it++) {
            int idx = it * 256 + tid;
            int row = idx & 63;              // key
            int c4  = idx >> 6;              // dim group 0..31
            float4 v = *(const float4*)(Vb + (size_t)(k0 + row) * KROW + c4 * 4);
            Vt[(c4 * 4 + 0) * AVS + row] = tf32rn(v.x);
            Vt[(c4 * 4 + 1) * AVS + row] = tf32rn(v.y);
            Vt[(c4 * 4 + 2) * AVS + row] = tf32rn(v.z);
            Vt[(c4 * 4 + 3) * AVS + row] = tf32rn(v.w);
        }
        __syncthreads();

        // ---- scores S = Q K^T : 8 n-tiles of 16x8 ----
        float sc[8][4];
#pragma unroll
        for (int ni = 0; ni < 8; ni++)
#pragma unroll
            for (int r = 0; r < 4; r++) sc[ni][r] = 0.0f;

#pragma unroll
        for (int kk = 0; kk < 16; kk++) {
            uint32_t a[4], bfr[8][2];
            const float* ap = Qs + (wid * 16 + g) * AQS + kk * 8 + t;
            a[0] = __float_as_uint(ap[0]);
            a[1] = __float_as_uint(ap[8 * AQS]);
            a[2] = __float_as_uint(ap[4]);
            a[3] = __float_as_uint(ap[8 * AQS + 4]);
#pragma unroll
            for (int ni = 0; ni < 8; ni++) {
                const float* bp = Ks + (ni * 8 + g) * AQS + kk * 8 + t;
                bfr[ni][0] = __float_as_uint(bp[0]);
                bfr[ni][1] = __float_as_uint(bp[4]);
            }
#pragma unroll
            for (int ni = 0; ni < 8; ni++)
                mma_tf32(sc[ni], a, bfr[ni]);
        }

        // ---- causal mask (only near the diagonal) ----
        if (k0 + 63 > qbase) {
#pragma unroll
            for (int ni = 0; ni < 8; ni++) {
                int c0 = k0 + ni * 8 + 2 * t;
                int r0 = qbase + g;
                if (c0 > r0)     sc[ni][0] = -1e30f;
                if (c0 + 1 > r0) sc[ni][1] = -1e30f;
                if (c0 > r0 + 8)     sc[ni][2] = -1e30f;
                if (c0 + 1 > r0 + 8) sc[ni][3] = -1e30f;
            }
        }

        // ---- online softmax (rows g and g+8) ----
        float mx0 = -1e30f, mx1 = -1e30f;
#pragma unroll
        for (int ni = 0; ni < 8; ni++) {
            mx0 = fmaxf(mx0, fmaxf(sc[ni][0], sc[ni][1]));
            mx1 = fmaxf(mx1, fmaxf(sc[ni][2], sc[ni][3]));
        }
        mx0 = fmaxf(mx0, __shfl_xor_sync(0xffffffffu, mx0, 1));
        mx0 = fmaxf(mx0, __shfl_xor_sync(0xffffffffu, mx0, 2));
        mx1 = fmaxf(mx1, __shfl_xor_sync(0xffffffffu, mx1, 1));
        mx1 = fmaxf(mx1, __shfl_xor_sync(0xffffffffu, mx1, 2));

        float mn0 = fmaxf(m0r, mx0);
        float mn1 = fmaxf(m1r, mx1);
        float cr0 = exp2p(m0r - mn0);
        float cr1 = exp2p(m1r - mn1);
        m0r = mn0; m1r = mn1;

        float rs0 = 0.0f, rs1 = 0.0f;
        float* pw0 = Ps + (wid * 16 + g) * AVS;
        float* pw1 = pw0 + 8 * AVS;
#pragma unroll
        for (int ni = 0; ni < 8; ni++) {
            float p0 = exp2p(sc[ni][0] - mn0);
            float p1 = exp2p(sc[ni][1] - mn0);
            float p2 = exp2p(sc[ni][2] - mn1);
            float p3 = exp2p(sc[ni][3] - mn1);
            rs0 += p0 + p1;
            rs1 += p2 + p3;
            *(float2*)(pw0 + ni * 8 + 2 * t) = make_float2(tf32rn(p0), tf32rn(p1));
            *(float2*)(pw1 + ni * 8 + 2 * t) = make_float2(tf32rn(p2), tf32rn(p3));
        }
        rs0 += __shfl_xor_sync(0xffffffffu, rs0, 1);
        rs0 += __shfl_xor_sync(0xffffffffu, rs0, 2);
        rs1 += __shfl_xor_sync(0xffffffffu, rs1, 1);
        rs1 += __shfl_xor_sync(0xffffffffu, rs1, 2);
        l0r = l0r * cr0 + rs0;
        l1r = l1r * cr1 + rs1;

#pragma unroll
        for (int ni = 0; ni < 16; ni++) {
            oa[ni][0] *= cr0; oa[ni][1] *= cr0;
            oa[ni][2] *= cr1; oa[ni][3] *= cr1;
        }
        __syncwarp();

        // ---- O += P V : 16 n-tiles (dims), 8 k-steps (keys) ----
#pragma unroll
        for (int kk = 0; kk < 8; kk++) {
            uint32_t a[4];
            const float* ap = Ps + (wid * 16 + g) * AVS + kk * 8 + t;
            a[0] = __float_as_uint(ap[0]);
            a[1] = __float_as_uint(ap[8 * AVS]);
            a[2] = __float_as_uint(ap[4]);
            a[3] = __float_as_uint(ap[8 * AVS + 4]);
#pragma unroll
            for (int ni = 0; ni < 16; ni++) {
                uint32_t bfr[2];
                const float* bp = Vt + (ni * 8 + g) * AVS + kk * 8 + t;
                bfr[0] = __float_as_uint(bp[0]);
                bfr[1] = __float_as_uint(bp[4]);
                mma_tf32(oa[ni], a, bfr);
            }
        }
        __syncthreads();   // before next tile overwrites Ks/Vt
    }

    // ---- epilogue: O / l, tf32-rounded for the O-projection ----
    float inv0 = 1.0f / l0r;
    float inv1 = 1.0f / l1r;
    float* o0 = O + (size_t)((size_t)b * SEQ + qbase + g) * QROW + h * HD;
    float* o1 = o0 + (size_t)8 * QROW;
#pragma unroll
    for (int ni = 0; ni < 16; ni++) {
        *(float2*)(o0 + ni * 8 + 2 * t) =
            make_float2(tf32rn(oa[ni][0] * inv0), tf32rn(oa[ni][1] * inv0));
        *(float2*)(o1 + ni * 8 + 2 * t) =
            make_float2(tf32rn(oa[ni][2] * inv1), tf32rn(oa[ni][3] * inv1));
    }
}

// =================================================================
extern "C" void kernel_launch(void* const* d_in, const int* in_sizes, int n_in,
                              void* d_out, int out_size)
{
    const float* hs   = (const float*)d_in[0];
    const float* cosb = (const float*)d_in[1];
    const float* sinb = (const float*)d_in[2];
    const float* wq   = (const float*)d_in[3];
    const float* wk   = (const float*)d_in[4];
    const float* wv   = (const float*)d_in[5];
    const float* wo   = (const float*)d_in[6];
    float* out = (float*)d_out;

    float *q, *k, *v, *attn, *hsc, *wqc, *wkc, *wvc, *woc;
    cudaGetSymbolAddress((void**)&q,    g_q);
    cudaGetSymbolAddress((void**)&k,    g_k);
    cudaGetSymbolAddress((void**)&v,    g_v);
    cudaGetSymbolAddress((void**)&attn, g_attn);
    cudaGetSymbolAddress((void**)&hsc,  g_hsc);
    cudaGetSymbolAddress((void**)&wqc,  g_wqc);
    cudaGetSymbolAddress((void**)&wkc,  g_wkc);
    cudaGetSymbolAddress((void**)&wvc,  g_wvc);
    cudaGetSymbolAddress((void**)&woc,  g_woc);

    cudaFuncSetAttribute(gemm_mma, cudaFuncAttributeMaxDynamicSharedMemorySize, GEMM_SMEM);
    cudaFuncSetAttribute(attn_mma, cudaFuncAttributeMaxDynamicSharedMemorySize, ATTN_SMEM);

    // tf32 RN pre-rounding of GEMM operands
    const long nHS = (long)TOKENS * HID / 4;
    const long nWQ = (long)QROW * HID / 4;
    const long nWK = (long)KROW * HID / 4;
    tf32_round_kernel<<<(nHS + 255) / 256, 256>>>((const float4*)hs, (float4*)hsc, nHS);
    tf32_round_kernel<<<(nWQ + 255) / 256, 256>>>((const float4*)wq, (float4*)wqc, nWQ);
    tf32_round_kernel<<<(nWK + 255) / 256, 256>>>((const float4*)wk, (float4*)wkc, nWK);
    tf32_round_kernel<<<(nWK + 255) / 256, 256>>>((const float4*)wv, (float4*)wvc, nWK);
    tf32_round_kernel<<<(nWQ + 255) / 256, 256>>>((const float4*)wo, (float4*)woc, nWQ);

    // QKV projections (tf32 mma.sync)
    gemm_mma<<<dim3(QROW / 256, TOKENS / 128), 256, GEMM_SMEM>>>(hsc, wqc, q, TOKENS, QROW, HID);
    gemm_mma<<<dim3(KROW / 256, TOKENS / 128), 256, GEMM_SMEM>>>(hsc, wkc, k, TOKENS, KROW, HID);
    gemm_mma<<<dim3(KROW / 256, TOKENS / 128), 256, GEMM_SMEM>>>(hsc, wvc, v, TOKENS, KROW, HID);

    // RoPE; Q scale folds 1/sqrt(128) * log2(e) so attention uses 2^x
    const float qscale = 0.08838834764831845f * 1.4426950408889634f;
    rope_kernel<<<(TOKENS * NH  * 64) / 256, 256>>>(q, cosb, sinb, NH,  qscale);
    rope_kernel<<<(TOKENS * NKV * 64) / 256, 256>>>(k, cosb, sinb, NKV, 1.0f);

    // Flash attention (tf32 mma.sync)
    attn_mma<<<dim3(SEQ / 128, BATCH * NH), 256, ATTN_SMEM>>>(q, k, v, attn);

    // Output projection
    gemm_mma<<<dim3(HID / 256, TOKENS / 128), 256, GEMM_SMEM>>>(attn, woc, out, TOKENS, HID, QROW);
}

// round 5
// speedup vs baseline: 3.7411x; 1.0594x over previous
#include <cuda_runtime.h>
#include <cuda_bf16.h>
#include <math.h>
#include <cstdint>

// Problem constants
#define BATCH 2
#define SEQ   2048
#define HID   4096
#define NH    32
#define NKV   8
#define HD    128
#define TOKENS (BATCH*SEQ)          // 4096
#define QROW (NH*HD)                // 4096
#define KROW (NKV*HD)               // 1024

// ---------------- scratch (no cudaMalloc allowed) ----------------
__device__ float g_q[(size_t)TOKENS * QROW];     // 64 MB
__device__ float g_k[(size_t)TOKENS * KROW];     // 16 MB
__device__ float g_v[(size_t)TOKENS * KROW];     // 16 MB
__device__ float g_attn[(size_t)TOKENS * QROW];  // 64 MB
// tf32-rounded operand copies
__device__ float g_hsc[(size_t)TOKENS * HID];    // 64 MB
__device__ float g_wqc[(size_t)QROW * HID];      // 64 MB
__device__ float g_wkc[(size_t)KROW * HID];      // 16 MB
__device__ float g_wvc[(size_t)KROW * HID];      // 16 MB
__device__ float g_woc[(size_t)HID * QROW];      // 64 MB

// ---------------- helpers ----------------
__device__ __forceinline__ uint32_t sa(const void* p) {
    return (uint32_t)__cvta_generic_to_shared(p);
}
__device__ __forceinline__ void cp_async16(uint32_t s, const void* g) {
    asm volatile("cp.async.cg.shared.global [%0], [%1], 16;" :: "r"(s), "l"(g));
}
__device__ __forceinline__ void cp_commit() {
    asm volatile("cp.async.commit_group;" ::: "memory");
}
template <int N>
__device__ __forceinline__ void cp_wait() {
    asm volatile("cp.async.wait_group %0;" :: "n"(N) : "memory");
}

__device__ __forceinline__ void mma_tf32(float* d, const uint32_t* a, const uint32_t* b) {
    asm volatile(
        "mma.sync.aligned.m16n8k8.row.col.f32.tf32.tf32.f32 "
        "{%0,%1,%2,%3}, {%4,%5,%6,%7}, {%8,%9}, {%0,%1,%2,%3};"
        : "+f"(d[0]), "+f"(d[1]), "+f"(d[2]), "+f"(d[3])
        : "r"(a[0]), "r"(a[1]), "r"(a[2]), "r"(a[3]), "r"(b[0]), "r"(b[1]));
}

__device__ __forceinline__ float tf32rn(float x) {
    uint32_t u;
    asm("cvt.rn.tf32.f32 %0, %1;" : "=r"(u) : "f"(x));
    return __uint_as_float(u);
}

// fast 2^x via FMA polynomial (avoids MUFU bottleneck; rel err ~1.5e-5)
__device__ __forceinline__ float exp2p(float x) {
    x = fmaxf(x, -126.0f);
    int   i = __float2int_rd(x);
    float f = x - (float)i;
    float p = 1.54035303934e-4f;
    p = fmaf(p, f, 1.33335581464e-3f);
    p = fmaf(p, f, 9.61812910763e-3f);
    p = fmaf(p, f, 5.55041086648e-2f);
    p = fmaf(p, f, 2.40226506959e-1f);
    p = fmaf(p, f, 6.93147180560e-1f);
    p = fmaf(p, f, 1.0f);
    return __int_as_float((i + 127) << 23) * p;
}

// =================================================================
// tf32 round-to-nearest conversion (elementwise, float4)
// =================================================================
__global__ __launch_bounds__(256)
void tf32_round_kernel(const float4* __restrict__ in, float4* __restrict__ out, long n4)
{
    long i = (long)blockIdx.x * blockDim.x + threadIdx.x;
    if (i >= n4) return;
    float4 v = in[i];
    out[i] = make_float4(tf32rn(v.x), tf32rn(v.y), tf32rn(v.z), tf32rn(v.w));
}

// =================================================================
// tf32 mma.sync GEMM:  C[m,n] = sum_k A[m,k]*B[n,k]   (R3, passing)
// =================================================================
#define GSTRIDE 36
#define A_FLOATS (128 * GSTRIDE)
#define B_FLOATS (256 * GSTRIDE)
#define STAGE_FLOATS (A_FLOATS + B_FLOATS)
#define GEMM_SMEM (2 * STAGE_FLOATS * 4)

__global__ __launch_bounds__(256, 1)
void gemm_mma(const float* __restrict__ A, const float* __restrict__ B,
              float* __restrict__ C, int M, int N, int K)
{
    extern __shared__ float sm[];

    const int tid = threadIdx.x;
    const int wid = tid >> 5;
    const int lane = tid & 31;
    const int g = lane >> 2;
    const int t = lane & 3;
    const int wm = wid & 1;
    const int wn = wid >> 1;
    const int m0 = blockIdx.y * 128;
    const int n0 = blockIdx.x * 256;

    const float* Ag = A + (size_t)m0 * K;
    const float* Bg = B + (size_t)n0 * K;

    auto load_stage = [&](int kt, int st) {
        float* As = sm + st * STAGE_FLOATS;
        float* Bs = As + A_FLOATS;
        const float* ap = Ag + kt * 32;
        const float* bp = Bg + kt * 32;
#pragma unroll
        for (int r = 0; r < 4; r++) {
            int c = r * 256 + tid;
            int row = c >> 3;
            int c4  = (c & 7) * 4;
            cp_async16(sa(As + row * GSTRIDE + c4), ap + (size_t)row * K + c4);
        }
#pragma unroll
        for (int r = 0; r < 8; r++) {
            int c = r * 256 + tid;
            int row = c >> 3;
            int c4  = (c & 7) * 4;
            cp_async16(sa(Bs + row * GSTRIDE + c4), bp + (size_t)row * K + c4);
        }
        cp_commit();
    };

    float d[4][8][4];
#pragma unroll
    for (int mi = 0; mi < 4; mi++)
#pragma unroll
        for (int ni = 0; ni < 8; ni++)
#pragma unroll
            for (int r = 0; r < 4; r++) d[mi][ni][r] = 0.0f;

    const int NT = K / 32;
    load_stage(0, 0);

    for (int kt = 0; kt < NT; kt++) {
        const int st = kt & 1;
        if (kt + 1 < NT) { load_stage(kt + 1, st ^ 1); cp_wait<1>(); }
        else             { cp_wait<0>(); }
        __syncthreads();

        const float* As = sm + st * STAGE_FLOATS;
        const float* Bs = As + A_FLOATS;

#pragma unroll
        for (int kk = 0; kk < 4; kk++) {
            uint32_t a[4][4], b[8][2];
#pragma unroll
            for (int mi = 0; mi < 4; mi++) {
                const float* ap = As + (wm * 64 + mi * 16 + g) * GSTRIDE + kk * 8 + t;
                a[mi][0] = __float_as_uint(ap[0]);
                a[mi][1] = __float_as_uint(ap[8 * GSTRIDE]);
                a[mi][2] = __float_as_uint(ap[4]);
                a[mi][3] = __float_as_uint(ap[8 * GSTRIDE + 4]);
            }
#pragma unroll
            for (int ni = 0; ni < 8; ni++) {
                const float* bp = Bs + (wn * 64 + ni * 8 + g) * GSTRIDE + kk * 8 + t;
                b[ni][0] = __float_as_uint(bp[0]);
                b[ni][1] = __float_as_uint(bp[4]);
            }
#pragma unroll
            for (int mi = 0; mi < 4; mi++)
#pragma unroll
                for (int ni = 0; ni < 8; ni++)
                    mma_tf32(d[mi][ni], a[mi], b[ni]);
        }
        __syncthreads();
    }

#pragma unroll
    for (int mi = 0; mi < 4; mi++) {
        const int r0 = m0 + wm * 64 + mi * 16 + g;
        float* c0p = C + (size_t)r0 * N + n0 + wn * 64;
        float* c1p = c0p + (size_t)8 * N;
#pragma unroll
        for (int ni = 0; ni < 8; ni++) {
            *(float2*)(c0p + ni * 8 + t * 2) = make_float2(d[mi][ni][0], d[mi][ni][1]);
            *(float2*)(c1p + ni * 8 + t * 2) = make_float2(d[mi][ni][2], d[mi][ni][3]);
        }
    }
}

// =================================================================
// RoPE (in place), folds scale into Q; output rounded to tf32
// (consumed only by the tensor-core attention).
// =================================================================
__global__ __launch_bounds__(256)
void rope_kernel(float* __restrict__ x, const float* __restrict__ cosb,
                 const float* __restrict__ sinb, int heads, float scale)
{
    long idx = (long)blockIdx.x * blockDim.x + threadIdx.x;
    long total = (long)TOKENS * heads * 64;
    if (idx >= total) return;
    int d = (int)(idx & 63);
    long t2 = idx >> 6;
    int h = (int)(t2 % heads);
    long tok = t2 / heads;
    float* row = x + (tok * heads + h) * HD;
    float c0 = cosb[tok * HD + d];
    float s0 = sinb[tok * HD + d];
    float c1 = cosb[tok * HD + d + 64];
    float s1 = sinb[tok * HD + d + 64];
    float a = row[d];
    float b = row[d + 64];
    row[d]      = tf32rn((a * c0 - b * s0) * scale);
    row[d + 64] = tf32rn((b * c1 + a * s1) * scale);
}

// =================================================================
// Tensor-core flash attention (causal, GQA 4:1), tf32 mma.sync,
// cp.async double-buffered K/V, Q fragments register-resident.
// Q pre-scaled by (1/sqrt(128))*log2(e) and tf32-rounded upstream.
// CTA: 128 queries x 1 head. 8 warps x 16 query rows. Key tile 64.
// Smem: 2 stages x (Ks[64][132] + Vs[64][136]) + Ps[128][68].
// =================================================================
#define AKS 132
#define AVSTR 136
#define APS 68
#define KS_FLOATS (64 * AKS)                  // 8448
#define VS_FLOATS (64 * AVSTR)                // 8704
#define STG_FLOATS (KS_FLOATS + VS_FLOATS)    // 17152
#define PS_OFF (2 * STG_FLOATS)               // 34304 floats
#define ATTN_SMEM ((PS_OFF + 128 * APS) * 4)  // 172032 B

__global__ __launch_bounds__(256, 1)
void attn_mma(const float* __restrict__ Q, const float* __restrict__ K,
              const float* __restrict__ V, float* __restrict__ O)
{
    extern __shared__ float sm[];

    const int tid = threadIdx.x;
    const int wid = tid >> 5;
    const int lane = tid & 31;
    const int g = lane >> 2;
    const int t = lane & 3;

    const int bh = blockIdx.y;
    const int b   = bh >> 5;
    const int h   = bh & 31;
    const int kvh = h >> 2;
    const int qt  = (int)(gridDim.x - 1 - blockIdx.x);
    const int q0  = qt * 128;

    const float* Qb = Q + (size_t)b * SEQ * QROW + h * HD;
    const float* Kb = K + (size_t)b * SEQ * KROW + kvh * HD;
    const float* Vb = V + (size_t)b * SEQ * KROW + kvh * HD;

    // ---- stage Q into smem (reuses stage-0 region), extract fragments ----
    {
#pragma unroll
        for (int it = 0; it < 16; it++) {
            int idx = it * 256 + tid;            // 0..4095
            int row = idx >> 5;
            int c4  = (idx & 31) * 4;
            cp_async16(sa(sm + row * AKS + c4),
                       Qb + (size_t)(q0 + row) * QROW + c4);
        }
        cp_commit();
        cp_wait<0>();
        __syncthreads();
    }

    uint32_t qa[16][4];
#pragma unroll
    for (int kk = 0; kk < 16; kk++) {
        const float* ap = sm + (wid * 16 + g) * AKS + kk * 8 + t;
        qa[kk][0] = __float_as_uint(ap[0]);
        qa[kk][1] = __float_as_uint(ap[8 * AKS]);
        qa[kk][2] = __float_as_uint(ap[4]);
        qa[kk][3] = __float_as_uint(ap[8 * AKS + 4]);
    }
    __syncthreads();

    const int qbase = q0 + wid * 16;

    float m0r = -1e30f, m1r = -1e30f, l0r = 0.0f, l1r = 0.0f;
    float oa[16][4];
#pragma unroll
    for (int ni = 0; ni < 16; ni++)
#pragma unroll
        for (int r = 0; r < 4; r++) oa[ni][r] = 0.0f;

    const int nkt = qt * 2 + 2;            // causal key tiles (>= 2)

    // ---- K/V stage loader: K 64x128 (stride 132) + V 64x128 (stride 136) ----
    auto load_kv = [&](int kt, int st) {
        float* Ks = sm + st * STG_FLOATS;
        float* Vs = Ks + KS_FLOATS;
        const int k0 = kt * 64;
#pragma unroll
        for (int it = 0; it < 8; it++) {
            int idx = it * 256 + tid;            // 0..2047
            int row = idx >> 5;
            int c4  = (idx & 31) * 4;
            cp_async16(sa(Ks + row * AKS + c4),
                       Kb + (size_t)(k0 + row) * KROW + c4);
        }
#pragma unroll
        for (int it = 0; it < 8; it++) {
            int idx = it * 256 + tid;
            int row = idx >> 5;
            int c4  = (idx & 31) * 4;
            cp_async16(sa(Vs + row * AVSTR + c4),
                       Vb + (size_t)(k0 + row) * KROW + c4);
        }
        cp_commit();
    };

    load_kv(0, 0);
    load_kv(1, 1);

    for (int kt = 0; kt < nkt; kt++) {
        const int st = kt & 1;
        const int k0 = kt * 64;
        if (kt + 1 < nkt) cp_wait<1>();
        else              cp_wait<0>();
        __syncthreads();

        const float* Ks = sm + st * STG_FLOATS;
        const float* Vs = Ks + KS_FLOATS;

        // ---- scores S = Q K^T : 8 n-tiles of 16x8, Q in registers ----
        float sc[8][4];
#pragma unroll
        for (int ni = 0; ni < 8; ni++)
#pragma unroll
            for (int r = 0; r < 4; r++) sc[ni][r] = 0.0f;

#pragma unroll
        for (int kk = 0; kk < 16; kk++) {
            uint32_t bfr[8][2];
#pragma unroll
            for (int ni = 0; ni < 8; ni++) {
                const float* bp = Ks + (ni * 8 + g) * AKS + kk * 8 + t;
                bfr[ni][0] = __float_as_uint(bp[0]);
                bfr[ni][1] = __float_as_uint(bp[4]);
            }
#pragma unroll
            for (int ni = 0; ni < 8; ni++)
                mma_tf32(sc[ni], qa[kk], bfr[ni]);
        }

        // ---- causal mask (only near the diagonal) ----
        if (k0 + 63 > qbase) {
#pragma unroll
            for (int ni = 0; ni < 8; ni++) {
                int c0 = k0 + ni * 8 + 2 * t;
                int r0 = qbase + g;
                if (c0 > r0)     sc[ni][0] = -1e30f;
                if (c0 + 1 > r0) sc[ni][1] = -1e30f;
                if (c0 > r0 + 8)     sc[ni][2] = -1e30f;
                if (c0 + 1 > r0 + 8) sc[ni][3] = -1e30f;
            }
        }

        // ---- online softmax (rows g and g+8) ----
        float mx0 = -1e30f, mx1 = -1e30f;
#pragma unroll
        for (int ni = 0; ni < 8; ni++) {
            mx0 = fmaxf(mx0, fmaxf(sc[ni][0], sc[ni][1]));
            mx1 = fmaxf(mx1, fmaxf(sc[ni][2], sc[ni][3]));
        }
        mx0 = fmaxf(mx0, __shfl_xor_sync(0xffffffffu, mx0, 1));
        mx0 = fmaxf(mx0, __shfl_xor_sync(0xffffffffu, mx0, 2));
        mx1 = fmaxf(mx1, __shfl_xor_sync(0xffffffffu, mx1, 1));
        mx1 = fmaxf(mx1, __shfl_xor_sync(0xffffffffu, mx1, 2));

        float mn0 = fmaxf(m0r, mx0);
        float mn1 = fmaxf(m1r, mx1);
        float cr0 = exp2p(m0r - mn0);
        float cr1 = exp2p(m1r - mn1);
        m0r = mn0; m1r = mn1;

        float rs0 = 0.0f, rs1 = 0.0f;
        float* pw0 = sm + PS_OFF + (wid * 16 + g) * APS;
        float* pw1 = pw0 + 8 * APS;
#pragma unroll
        for (int ni = 0; ni < 8; ni++) {
            float p0 = exp2p(sc[ni][0] - mn0);
            float p1 = exp2p(sc[ni][1] - mn0);
            float p2 = exp2p(sc[ni][2] - mn1);
            float p3 = exp2p(sc[ni][3] - mn1);
            rs0 += p0 + p1;
            rs1 += p2 + p3;
            *(float2*)(pw0 + ni * 8 + 2 * t) = make_float2(tf32rn(p0), tf32rn(p1));
            *(float2*)(pw1 + ni * 8 + 2 * t) = make_float2(tf32rn(p2), tf32rn(p3));
        }
        rs0 += __shfl_xor_sync(0xffffffffu, rs0, 1);
        rs0 += __shfl_xor_sync(0xffffffffu, rs0, 2);
        rs1 += __shfl_xor_sync(0xffffffffu, rs1, 1);
        rs1 += __shfl_xor_sync(0xffffffffu, rs1, 2);
        l0r = l0r * cr0 + rs0;
        l1r = l1r * cr1 + rs1;

#pragma unroll
        for (int ni = 0; ni < 16; ni++) {
            oa[ni][0] *= cr0; oa[ni][1] *= cr0;
            oa[ni][2] *= cr1; oa[ni][3] *= cr1;
        }
        __syncwarp();

        // ---- O += P V : V row-major (stride 136, conflict-free) ----
#pragma unroll
        for (int kk = 0; kk < 8; kk++) {
            uint32_t a[4];
            const float* ap = sm + PS_OFF + (wid * 16 + g) * APS + kk * 8 + t;
            a[0] = __float_as_uint(ap[0]);
            a[1] = __float_as_uint(ap[8 * APS]);
            a[2] = __float_as_uint(ap[4]);
            a[3] = __float_as_uint(ap[8 * APS + 4]);
#pragma unroll
            for (int ni = 0; ni < 16; ni++) {
                uint32_t bfr[2];
                const float* bp = Vs + (kk * 8 + t) * AVSTR + ni * 8 + g;
                bfr[0] = __float_as_uint(bp[0]);
                bfr[1] = __float_as_uint(bp[4 * AVSTR]);
                mma_tf32(oa[ni], a, bfr);
            }
        }
        __syncthreads();   // all warps done with stage st
        if (kt + 2 < nkt) load_kv(kt + 2, st);
    }

    // ---- epilogue: O / l, tf32-rounded for the O-projection ----
    float inv0 = 1.0f / l0r;
    float inv1 = 1.0f / l1r;
    float* o0 = O + (size_t)((size_t)b * SEQ + qbase + g) * QROW + h * HD;
    float* o1 = o0 + (size_t)8 * QROW;
#pragma unroll
    for (int ni = 0; ni < 16; ni++) {
        *(float2*)(o0 + ni * 8 + 2 * t) =
            make_float2(tf32rn(oa[ni][0] * inv0), tf32rn(oa[ni][1] * inv0));
        *(float2*)(o1 + ni * 8 + 2 * t) =
            make_float2(tf32rn(oa[ni][2] * inv1), tf32rn(oa[ni][3] * inv1));
    }
}

// =================================================================
extern "C" void kernel_launch(void* const* d_in, const int* in_sizes, int n_in,
                              void* d_out, int out_size)
{
    const float* hs   = (const float*)d_in[0];
    const float* cosb = (const float*)d_in[1];
    const float* sinb = (const float*)d_in[2];
    const float* wq   = (const float*)d_in[3];
    const float* wk   = (const float*)d_in[4];
    const float* wv   = (const float*)d_in[5];
    const float* wo   = (const float*)d_in[6];
    float* out = (float*)d_out;

    float *q, *k, *v, *attn, *hsc, *wqc, *wkc, *wvc, *woc;
    cudaGetSymbolAddress((void**)&q,    g_q);
    cudaGetSymbolAddress((void**)&k,    g_k);
    cudaGetSymbolAddress((void**)&v,    g_v);
    cudaGetSymbolAddress((void**)&attn, g_attn);
    cudaGetSymbolAddress((void**)&hsc,  g_hsc);
    cudaGetSymbolAddress((void**)&wqc,  g_wqc);
    cudaGetSymbolAddress((void**)&wkc,  g_wkc);
    cudaGetSymbolAddress((void**)&wvc,  g_wvc);
    cudaGetSymbolAddress((void**)&woc,  g_woc);

    cudaFuncSetAttribute(gemm_mma, cudaFuncAttributeMaxDynamicSharedMemorySize, GEMM_SMEM);
    cudaFuncSetAttribute(attn_mma, cudaFuncAttributeMaxDynamicSharedMemorySize, ATTN_SMEM);

    // tf32 RN pre-rounding of GEMM operands
    const long nHS = (long)TOKENS * HID / 4;
    const long nWQ = (long)QROW * HID / 4;
    const long nWK = (long)KROW * HID / 4;
    tf32_round_kernel<<<(nHS + 255) / 256, 256>>>((const float4*)hs, (float4*)hsc, nHS);
    tf32_round_kernel<<<(nWQ + 255) / 256, 256>>>((const float4*)wq, (float4*)wqc, nWQ);
    tf32_round_kernel<<<(nWK + 255) / 256, 256>>>((const float4*)wk, (float4*)wkc, nWK);
    tf32_round_kernel<<<(nWK + 255) / 256, 256>>>((const float4*)wv, (float4*)wvc, nWK);
    tf32_round_kernel<<<(nWQ + 255) / 256, 256>>>((const float4*)wo, (float4*)woc, nWQ);

    // QKV projections (tf32 mma.sync)
    gemm_mma<<<dim3(QROW / 256, TOKENS / 128), 256, GEMM_SMEM>>>(hsc, wqc, q, TOKENS, QROW, HID);
    gemm_mma<<<dim3(KROW / 256, TOKENS / 128), 256, GEMM_SMEM>>>(hsc, wkc, k, TOKENS, KROW, HID);
    gemm_mma<<<dim3(KROW / 256, TOKENS / 128), 256, GEMM_SMEM>>>(hsc, wvc, v, TOKENS, KROW, HID);

    // RoPE (tf32-rounded output); Q scale folds 1/sqrt(128) * log2(e)
    const float qscale = 0.08838834764831845f * 1.4426950408889634f;
    rope_kernel<<<(TOKENS * NH  * 64) / 256, 256>>>(q, cosb, sinb, NH,  qscale);
    rope_kernel<<<(TOKENS * NKV * 64) / 256, 256>>>(k, cosb, sinb, NKV, 1.0f);
    // V rounded to tf32 (attention cp.asyncs raw bytes)
    const long nV = (long)TOKENS * KROW / 4;
    tf32_round_kernel<<<(nV + 255) / 256, 256>>>((const float4*)v, (float4*)v, nV);

    // Flash attention (tf32 mma.sync, pipelined)
    attn_mma<<<dim3(SEQ / 128, BATCH * NH), 256, ATTN_SMEM>>>(q, k, v, attn);

    // Output projection
    gemm_mma<<<dim3(HID / 256, TOKENS / 128), 256, GEMM_SMEM>>>(attn, woc, out, TOKENS, HID, QROW);
}

// round 6
// speedup vs baseline: 3.8482x; 1.0286x over previous
#include <cuda_runtime.h>
#include <cuda_bf16.h>
#include <math.h>
#include <cstdint>

// Problem constants
#define BATCH 2
#define SEQ   2048
#define HID   4096
#define NH    32
#define NKV   8
#define HD    128
#define TOKENS (BATCH*SEQ)          // 4096
#define QROW (NH*HD)                // 4096
#define KROW (NKV*HD)               // 1024
#define QKVW (QROW + 2*KROW)        // 6144 fused qkv row width

// ---------------- scratch (no cudaMalloc allowed) ----------------
__device__ float g_qkv[(size_t)TOKENS * QKVW];   // 100 MB (q|k|v per token)
__device__ float g_attn[(size_t)TOKENS * QROW];  // 64 MB
__device__ float g_hsc[(size_t)TOKENS * HID];    // 64 MB  (tf32-rounded hs)
__device__ float g_wqkv[(size_t)QKVW * HID];     // 100 MB (wq|wk|wv rows, tf32)
__device__ float g_woc[(size_t)HID * QROW];      // 64 MB  (tf32 wo)

// ---------------- helpers ----------------
__device__ __forceinline__ uint32_t sa(const void* p) {
    return (uint32_t)__cvta_generic_to_shared(p);
}
__device__ __forceinline__ void cp_async16(uint32_t s, const void* g) {
    asm volatile("cp.async.cg.shared.global [%0], [%1], 16;" :: "r"(s), "l"(g));
}
__device__ __forceinline__ void cp_commit() {
    asm volatile("cp.async.commit_group;" ::: "memory");
}
template <int N>
__device__ __forceinline__ void cp_wait() {
    asm volatile("cp.async.wait_group %0;" :: "n"(N) : "memory");
}

__device__ __forceinline__ void mma_tf32(float* d, const uint32_t* a, const uint32_t* b) {
    asm volatile(
        "mma.sync.aligned.m16n8k8.row.col.f32.tf32.tf32.f32 "
        "{%0,%1,%2,%3}, {%4,%5,%6,%7}, {%8,%9}, {%0,%1,%2,%3};"
        : "+f"(d[0]), "+f"(d[1]), "+f"(d[2]), "+f"(d[3])
        : "r"(a[0]), "r"(a[1]), "r"(a[2]), "r"(a[3]), "r"(b[0]), "r"(b[1]));
}

__device__ __forceinline__ float tf32rn(float x) {
    uint32_t u;
    asm("cvt.rn.tf32.f32 %0, %1;" : "=r"(u) : "f"(x));
    return __uint_as_float(u);
}

// hardware 2^x (MUFU) — frees the FMA pipe in the softmax section
__device__ __forceinline__ float ex2(float x) {
    float y;
    asm("ex2.approx.ftz.f32 %0, %1;" : "=f"(y) : "f"(x));
    return y;
}

// =================================================================
// tf32 round (elementwise, float4)
// =================================================================
__global__ __launch_bounds__(256)
void tf32_round_kernel(const float4* __restrict__ in, float4* __restrict__ out, long n4)
{
    long i = (long)blockIdx.x * blockDim.x + threadIdx.x;
    if (i >= n4) return;
    float4 v = in[i];
    out[i] = make_float4(tf32rn(v.x), tf32rn(v.y), tf32rn(v.z), tf32rn(v.w));
}

// =================================================================
// All weights rounded in ONE launch:
//   wq|wk|wv -> g_wqkv (stacked rows), wo -> g_woc
// =================================================================
#define NQ4 ((long)QROW * HID / 4)   // 4.19M
#define NK4 ((long)KROW * HID / 4)   // 1.05M
#define NO4 ((long)HID * QROW / 4)   // 4.19M
#define NW4_TOTAL (NQ4 + 2*NK4 + NO4)

__global__ __launch_bounds__(256)
void round_weights_kernel(const float4* __restrict__ wq, const float4* __restrict__ wk,
                          const float4* __restrict__ wv, const float4* __restrict__ wo,
                          float4* __restrict__ wqkv, float4* __restrict__ woc)
{
    long i = (long)blockIdx.x * blockDim.x + threadIdx.x;
    if (i >= NW4_TOTAL) return;
    float4 v;
    float4* dst;
    if (i < NQ4)                    { v = wq[i];               dst = wqkv + i; }
    else if (i < NQ4 + NK4)         { v = wk[i - NQ4];         dst = wqkv + i; }
    else if (i < NQ4 + 2*NK4)       { v = wv[i - NQ4 - NK4];   dst = wqkv + i; }
    else                            { v = wo[i - NQ4 - 2*NK4]; dst = woc + (i - NQ4 - 2*NK4); }
    *dst = make_float4(tf32rn(v.x), tf32rn(v.y), tf32rn(v.z), tf32rn(v.w));
}

// =================================================================
// tf32 mma.sync GEMM:  C[m,n] = sum_k A[m,k]*B[n,k]
// Optional tf32 rounding of C (roundC != 0).
// =================================================================
#define GSTRIDE 36
#define A_FLOATS (128 * GSTRIDE)
#define B_FLOATS (256 * GSTRIDE)
#define STAGE_FLOATS (A_FLOATS + B_FLOATS)
#define GEMM_SMEM (2 * STAGE_FLOATS * 4)

__global__ __launch_bounds__(256, 1)
void gemm_mma(const float* __restrict__ A, const float* __restrict__ B,
              float* __restrict__ C, int M, int N, int K, int roundC)
{
    extern __shared__ float sm[];

    const int tid = threadIdx.x;
    const int wid = tid >> 5;
    const int lane = tid & 31;
    const int g = lane >> 2;
    const int t = lane & 3;
    const int wm = wid & 1;
    const int wn = wid >> 1;
    const int m0 = blockIdx.y * 128;
    const int n0 = blockIdx.x * 256;

    const float* Ag = A + (size_t)m0 * K;
    const float* Bg = B + (size_t)n0 * K;

    auto load_stage = [&](int kt, int st) {
        float* As = sm + st * STAGE_FLOATS;
        float* Bs = As + A_FLOATS;
        const float* ap = Ag + kt * 32;
        const float* bp = Bg + kt * 32;
#pragma unroll
        for (int r = 0; r < 4; r++) {
            int c = r * 256 + tid;
            int row = c >> 3;
            int c4  = (c & 7) * 4;
            cp_async16(sa(As + row * GSTRIDE + c4), ap + (size_t)row * K + c4);
        }
#pragma unroll
        for (int r = 0; r < 8; r++) {
            int c = r * 256 + tid;
            int row = c >> 3;
            int c4  = (c & 7) * 4;
            cp_async16(sa(Bs + row * GSTRIDE + c4), bp + (size_t)row * K + c4);
        }
        cp_commit();
    };

    float d[4][8][4];
#pragma unroll
    for (int mi = 0; mi < 4; mi++)
#pragma unroll
        for (int ni = 0; ni < 8; ni++)
#pragma unroll
            for (int r = 0; r < 4; r++) d[mi][ni][r] = 0.0f;

    const int NT = K / 32;
    load_stage(0, 0);

    for (int kt = 0; kt < NT; kt++) {
        const int st = kt & 1;
        if (kt + 1 < NT) { load_stage(kt + 1, st ^ 1); cp_wait<1>(); }
        else             { cp_wait<0>(); }
        __syncthreads();

        const float* As = sm + st * STAGE_FLOATS;
        const float* Bs = As + A_FLOATS;

#pragma unroll
        for (int kk = 0; kk < 4; kk++) {
            uint32_t a[4][4], b[8][2];
#pragma unroll
            for (int mi = 0; mi < 4; mi++) {
                const float* ap = As + (wm * 64 + mi * 16 + g) * GSTRIDE + kk * 8 + t;
                a[mi][0] = __float_as_uint(ap[0]);
                a[mi][1] = __float_as_uint(ap[8 * GSTRIDE]);
                a[mi][2] = __float_as_uint(ap[4]);
                a[mi][3] = __float_as_uint(ap[8 * GSTRIDE + 4]);
            }
#pragma unroll
            for (int ni = 0; ni < 8; ni++) {
                const float* bp = Bs + (wn * 64 + ni * 8 + g) * GSTRIDE + kk * 8 + t;
                b[ni][0] = __float_as_uint(bp[0]);
                b[ni][1] = __float_as_uint(bp[4]);
            }
#pragma unroll
            for (int mi = 0; mi < 4; mi++)
#pragma unroll
                for (int ni = 0; ni < 8; ni++)
                    mma_tf32(d[mi][ni], a[mi], b[ni]);
        }
        __syncthreads();
    }

#pragma unroll
    for (int mi = 0; mi < 4; mi++) {
        const int r0 = m0 + wm * 64 + mi * 16 + g;
        float* c0p = C + (size_t)r0 * N + n0 + wn * 64;
        float* c1p = c0p + (size_t)8 * N;
        if (roundC) {
#pragma unroll
            for (int ni = 0; ni < 8; ni++) {
                *(float2*)(c0p + ni * 8 + t * 2) =
                    make_float2(tf32rn(d[mi][ni][0]), tf32rn(d[mi][ni][1]));
                *(float2*)(c1p + ni * 8 + t * 2) =
                    make_float2(tf32rn(d[mi][ni][2]), tf32rn(d[mi][ni][3]));
            }
        } else {
#pragma unroll
            for (int ni = 0; ni < 8; ni++) {
                *(float2*)(c0p + ni * 8 + t * 2) = make_float2(d[mi][ni][0], d[mi][ni][1]);
                *(float2*)(c1p + ni * 8 + t * 2) = make_float2(d[mi][ni][2], d[mi][ni][3]);
            }
        }
    }
}

// =================================================================
// RoPE (in place on a head-block inside the fused qkv row).
// x points at the first head of the block; token stride = QKVW.
// Output tf32-rounded.
// =================================================================
__global__ __launch_bounds__(256)
void rope_kernel(float* __restrict__ x, const float* __restrict__ cosb,
                 const float* __restrict__ sinb, int heads, float scale)
{
    long idx = (long)blockIdx.x * blockDim.x + threadIdx.x;
    long total = (long)TOKENS * heads * 64;
    if (idx >= total) return;
    int d = (int)(idx & 63);
    long t2 = idx >> 6;
    int h = (int)(t2 % heads);
    long tok = t2 / heads;
    float* row = x + tok * QKVW + h * HD;
    float c0 = cosb[tok * HD + d];
    float s0 = sinb[tok * HD + d];
    float c1 = cosb[tok * HD + d + 64];
    float s1 = sinb[tok * HD + d + 64];
    float a = row[d];
    float b = row[d + 64];
    row[d]      = tf32rn((a * c0 - b * s0) * scale);
    row[d + 64] = tf32rn((b * c1 + a * s1) * scale);
}

// =================================================================
// Tensor-core flash attention (causal, GQA 4:1), tf32 mma.sync,
// cp.async double-buffered K/V, Q fragments register-resident,
// MUFU 2^x. Reads fused qkv (token stride 6144).
// CTA: 128 queries x 1 head. 8 warps x 16 query rows. Key tile 64.
// =================================================================
#define AKS 132
#define AVSTR 136
#define APS 68
#define KS_FLOATS (64 * AKS)
#define VS_FLOATS (64 * AVSTR)
#define STG_FLOATS (KS_FLOATS + VS_FLOATS)
#define PS_OFF (2 * STG_FLOATS)
#define ATTN_SMEM ((PS_OFF + 128 * APS) * 4)  // 172032 B

__global__ __launch_bounds__(256, 1)
void attn_mma(const float* __restrict__ QKV, float* __restrict__ O)
{
    extern __shared__ float sm[];

    const int tid = threadIdx.x;
    const int wid = tid >> 5;
    const int lane = tid & 31;
    const int g = lane >> 2;
    const int t = lane & 3;

    const int bh = blockIdx.y;
    const int b   = bh >> 5;
    const int h   = bh & 31;
    const int kvh = h >> 2;
    const int qt  = (int)(gridDim.x - 1 - blockIdx.x);
    const int q0  = qt * 128;

    const float* Qb = QKV + (size_t)b * SEQ * QKVW + h * HD;
    const float* Kb = QKV + (size_t)b * SEQ * QKVW + QROW + kvh * HD;
    const float* Vb = QKV + (size_t)b * SEQ * QKVW + QROW + KROW + kvh * HD;

    // ---- stage Q into smem (stage-0 region), extract fragments ----
    {
#pragma unroll
        for (int it = 0; it < 16; it++) {
            int idx = it * 256 + tid;
            int row = idx >> 5;
            int c4  = (idx & 31) * 4;
            cp_async16(sa(sm + row * AKS + c4),
                       Qb + (size_t)(q0 + row) * QKVW + c4);
        }
        cp_commit();
        cp_wait<0>();
        __syncthreads();
    }

    uint32_t qa[16][4];
#pragma unroll
    for (int kk = 0; kk < 16; kk++) {
        const float* ap = sm + (wid * 16 + g) * AKS + kk * 8 + t;
        qa[kk][0] = __float_as_uint(ap[0]);
        qa[kk][1] = __float_as_uint(ap[8 * AKS]);
        qa[kk][2] = __float_as_uint(ap[4]);
        qa[kk][3] = __float_as_uint(ap[8 * AKS + 4]);
    }
    __syncthreads();

    const int qbase = q0 + wid * 16;

    float m0r = -1e30f, m1r = -1e30f, l0r = 0.0f, l1r = 0.0f;
    float oa[16][4];
#pragma unroll
    for (int ni = 0; ni < 16; ni++)
#pragma unroll
        for (int r = 0; r < 4; r++) oa[ni][r] = 0.0f;

    const int nkt = qt * 2 + 2;

    auto load_kv = [&](int kt, int st) {
        float* Ks = sm + st * STG_FLOATS;
        float* Vs = Ks + KS_FLOATS;
        const int k0 = kt * 64;
#pragma unroll
        for (int it = 0; it < 8; it++) {
            int idx = it * 256 + tid;
            int row = idx >> 5;
            int c4  = (idx & 31) * 4;
            cp_async16(sa(Ks + row * AKS + c4),
                       Kb + (size_t)(k0 + row) * QKVW + c4);
        }
#pragma unroll
        for (int it = 0; it < 8; it++) {
            int idx = it * 256 + tid;
            int row = idx >> 5;
            int c4  = (idx & 31) * 4;
            cp_async16(sa(Vs + row * AVSTR + c4),
                       Vb + (size_t)(k0 + row) * QKVW + c4);
        }
        cp_commit();
    };

    load_kv(0, 0);
    load_kv(1, 1);

    for (int kt = 0; kt < nkt; kt++) {
        const int st = kt & 1;
        const int k0 = kt * 64;
        if (kt + 1 < nkt) cp_wait<1>();
        else              cp_wait<0>();
        __syncthreads();

        const float* Ks = sm + st * STG_FLOATS;
        const float* Vs = Ks + KS_FLOATS;

        // ---- scores S = Q K^T ----
        float sc[8][4];
#pragma unroll
        for (int ni = 0; ni < 8; ni++)
#pragma unroll
            for (int r = 0; r < 4; r++) sc[ni][r] = 0.0f;

#pragma unroll
        for (int kk = 0; kk < 16; kk++) {
            uint32_t bfr[8][2];
#pragma unroll
            for (int ni = 0; ni < 8; ni++) {
                const float* bp = Ks + (ni * 8 + g) * AKS + kk * 8 + t;
                bfr[ni][0] = __float_as_uint(bp[0]);
                bfr[ni][1] = __float_as_uint(bp[4]);
            }
#pragma unroll
            for (int ni = 0; ni < 8; ni++)
                mma_tf32(sc[ni], qa[kk], bfr[ni]);
        }

        // ---- causal mask ----
        if (k0 + 63 > qbase) {
#pragma unroll
            for (int ni = 0; ni < 8; ni++) {
                int c0 = k0 + ni * 8 + 2 * t;
                int r0 = qbase + g;
                if (c0 > r0)     sc[ni][0] = -1e30f;
                if (c0 + 1 > r0) sc[ni][1] = -1e30f;
                if (c0 > r0 + 8)     sc[ni][2] = -1e30f;
                if (c0 + 1 > r0 + 8) sc[ni][3] = -1e30f;
            }
        }

        // ---- online softmax ----
        float mx0 = -1e30f, mx1 = -1e30f;
#pragma unroll
        for (int ni = 0; ni < 8; ni++) {
            mx0 = fmaxf(mx0, fmaxf(sc[ni][0], sc[ni][1]));
            mx1 = fmaxf(mx1, fmaxf(sc[ni][2], sc[ni][3]));
        }
        mx0 = fmaxf(mx0, __shfl_xor_sync(0xffffffffu, mx0, 1));
        mx0 = fmaxf(mx0, __shfl_xor_sync(0xffffffffu, mx0, 2));
        mx1 = fmaxf(mx1, __shfl_xor_sync(0xffffffffu, mx1, 1));
        mx1 = fmaxf(mx1, __shfl_xor_sync(0xffffffffu, mx1, 2));

        float mn0 = fmaxf(m0r, mx0);
        float mn1 = fmaxf(m1r, mx1);
        float cr0 = ex2(m0r - mn0);
        float cr1 = ex2(m1r - mn1);
        m0r = mn0; m1r = mn1;

        float rs0 = 0.0f, rs1 = 0.0f;
        float* pw0 = sm + PS_OFF + (wid * 16 + g) * APS;
        float* pw1 = pw0 + 8 * APS;
#pragma unroll
        for (int ni = 0; ni < 8; ni++) {
            float p0 = ex2(sc[ni][0] - mn0);
            float p1 = ex2(sc[ni][1] - mn0);
            float p2 = ex2(sc[ni][2] - mn1);
            float p3 = ex2(sc[ni][3] - mn1);
            rs0 += p0 + p1;
            rs1 += p2 + p3;
            *(float2*)(pw0 + ni * 8 + 2 * t) = make_float2(tf32rn(p0), tf32rn(p1));
            *(float2*)(pw1 + ni * 8 + 2 * t) = make_float2(tf32rn(p2), tf32rn(p3));
        }
        rs0 += __shfl_xor_sync(0xffffffffu, rs0, 1);
        rs0 += __shfl_xor_sync(0xffffffffu, rs0, 2);
        rs1 += __shfl_xor_sync(0xffffffffu, rs1, 1);
        rs1 += __shfl_xor_sync(0xffffffffu, rs1, 2);
        l0r = l0r * cr0 + rs0;
        l1r = l1r * cr1 + rs1;

#pragma unroll
        for (int ni = 0; ni < 16; ni++) {
            oa[ni][0] *= cr0; oa[ni][1] *= cr0;
            oa[ni][2] *= cr1; oa[ni][3] *= cr1;
        }
        __syncwarp();

        // ---- O += P V ----
#pragma unroll
        for (int kk = 0; kk < 8; kk++) {
            uint32_t a[4];
            const float* ap = sm + PS_OFF + (wid * 16 + g) * APS + kk * 8 + t;
            a[0] = __float_as_uint(ap[0]);
            a[1] = __float_as_uint(ap[8 * APS]);
            a[2] = __float_as_uint(ap[4]);
            a[3] = __float_as_uint(ap[8 * APS + 4]);
#pragma unroll
            for (int ni = 0; ni < 16; ni++) {
                uint32_t bfr[2];
                const float* bp = Vs + (kk * 8 + t) * AVSTR + ni * 8 + g;
                bfr[0] = __float_as_uint(bp[0]);
                bfr[1] = __float_as_uint(bp[4 * AVSTR]);
                mma_tf32(oa[ni], a, bfr);
            }
        }
        __syncthreads();
        if (kt + 2 < nkt) load_kv(kt + 2, st);
    }

    // ---- epilogue: O / l, tf32-rounded for the O-projection ----
    float inv0 = 1.0f / l0r;
    float inv1 = 1.0f / l1r;
    float* o0 = O + (size_t)((size_t)b * SEQ + qbase + g) * QROW + h * HD;
    float* o1 = o0 + (size_t)8 * QROW;
#pragma unroll
    for (int ni = 0; ni < 16; ni++) {
        *(float2*)(o0 + ni * 8 + 2 * t) =
            make_float2(tf32rn(oa[ni][0] * inv0), tf32rn(oa[ni][1] * inv0));
        *(float2*)(o1 + ni * 8 + 2 * t) =
            make_float2(tf32rn(oa[ni][2] * inv1), tf32rn(oa[ni][3] * inv1));
    }
}

// =================================================================
extern "C" void kernel_launch(void* const* d_in, const int* in_sizes, int n_in,
                              void* d_out, int out_size)
{
    const float* hs   = (const float*)d_in[0];
    const float* cosb = (const float*)d_in[1];
    const float* sinb = (const float*)d_in[2];
    const float* wq   = (const float*)d_in[3];
    const float* wk   = (const float*)d_in[4];
    const float* wv   = (const float*)d_in[5];
    const float* wo   = (const float*)d_in[6];
    float* out = (float*)d_out;

    float *qkv, *attn, *hsc, *wqkv, *woc;
    cudaGetSymbolAddress((void**)&qkv,  g_qkv);
    cudaGetSymbolAddress((void**)&attn, g_attn);
    cudaGetSymbolAddress((void**)&hsc,  g_hsc);
    cudaGetSymbolAddress((void**)&wqkv, g_wqkv);
    cudaGetSymbolAddress((void**)&woc,  g_woc);

    cudaFuncSetAttribute(gemm_mma, cudaFuncAttributeMaxDynamicSharedMemorySize, GEMM_SMEM);
    cudaFuncSetAttribute(attn_mma, cudaFuncAttributeMaxDynamicSharedMemorySize, ATTN_SMEM);

    // L0: round hidden states
    const long nHS = (long)TOKENS * HID / 4;
    tf32_round_kernel<<<(nHS + 255) / 256, 256>>>((const float4*)hs, (float4*)hsc, nHS);

    // L1: round all weights (wq|wk|wv stacked, wo separate)
    round_weights_kernel<<<(NW4_TOTAL + 255) / 256, 256>>>(
        (const float4*)wq, (const float4*)wk, (const float4*)wv, (const float4*)wo,
        (float4*)wqkv, (float4*)woc);

    // L2: fused QKV projection (N = 6144), epilogue tf32-rounds C
    gemm_mma<<<dim3(QKVW / 256, TOKENS / 128), 256, GEMM_SMEM>>>(
        hsc, wqkv, qkv, TOKENS, QKVW, HID, 1);

    // L3/L4: RoPE; Q scale folds 1/sqrt(128) * log2(e)
    const float qscale = 0.08838834764831845f * 1.4426950408889634f;
    rope_kernel<<<(TOKENS * NH  * 64) / 256, 256>>>(qkv, cosb, sinb, NH, qscale);
    rope_kernel<<<(TOKENS * NKV * 64) / 256, 256>>>(qkv + QROW, cosb, sinb, NKV, 1.0f);

    // L5: flash attention (profiled by -s 5 -c 1)
    attn_mma<<<dim3(SEQ / 128, BATCH * NH), 256, ATTN_SMEM>>>(qkv, attn);

    // L6: output projection
    gemm_mma<<<dim3(HID / 256, TOKENS / 128), 256, GEMM_SMEM>>>(
        attn, woc, out, TOKENS, HID, QROW, 0);
}